// round 2
// baseline (speedup 1.0000x reference)
#include <cuda_runtime.h>

typedef unsigned long long ull;

// Precomputed g = feats @ w_in[0:64,:] + b_in  (N x 64), N = 100000
__device__ float g_buf[100000 * 64];

__device__ __forceinline__ ull pack2(float lo, float hi) {
    ull r;
    asm("mov.b64 %0, {%1, %2};" : "=l"(r) : "f"(lo), "f"(hi));
    return r;
}
__device__ __forceinline__ ull bcast2(float v) { return pack2(v, v); }
__device__ __forceinline__ ull ffma2(ull a, ull b, ull c) {
    ull d;
    asm("fma.rn.f32x2 %0, %1, %2, %3;" : "=l"(d) : "l"(a), "l"(b), "l"(c));
    return d;
}
__device__ __forceinline__ void unpack2(ull v, float& lo, float& hi) {
    asm("mov.b64 {%0, %1}, %2;" : "=f"(lo), "=f"(hi) : "l"(v));
}

// ---------------------------------------------------------------------------
// Kernel 1: g[n, :] = feats[n, :] @ w_in[0:64, :] + b_in   (one thread per n)
// ---------------------------------------------------------------------------
__global__ void __launch_bounds__(128) precompute_kernel(
    const float* __restrict__ feats,
    const float* __restrict__ w_in,
    const float* __restrict__ b_in,
    int n_pts)
{
    __shared__ __align__(16) ull s_w[2048];  // w_in rows 0..63 (64x64 f32)
    for (int idx = threadIdx.x; idx < 2048; idx += 128)
        s_w[idx] = ((const ull*)w_in)[idx];
    __syncthreads();

    int n = blockIdx.x * 128 + threadIdx.x;
    if (n >= n_pts) return;

    float act[64];
    const float4* fp = (const float4*)(feats + (size_t)n * 64);
#pragma unroll
    for (int i = 0; i < 16; i++) {
        float4 v = fp[i];
        act[4 * i + 0] = v.x; act[4 * i + 1] = v.y;
        act[4 * i + 2] = v.z; act[4 * i + 3] = v.w;
    }

    ull acc[32];
    const ull* bp = (const ull*)b_in;
#pragma unroll
    for (int j = 0; j < 32; j++) acc[j] = bp[j];

#pragma unroll
    for (int i = 0; i < 64; i++) {
        ull a2 = bcast2(act[i]);
#pragma unroll
        for (int j = 0; j < 32; j += 2) {
            ulonglong2 w = *reinterpret_cast<const ulonglong2*>(&s_w[i * 32 + j]);
            acc[j]     = ffma2(a2, w.x, acc[j]);
            acc[j + 1] = ffma2(a2, w.y, acc[j + 1]);
        }
    }

    ull* gp = (ull*)(g_buf + (size_t)n * 64);
#pragma unroll
    for (int j = 0; j < 32; j++) gp[j] = acc[j];
}

// ---------------------------------------------------------------------------
// Kernel 2: per-edge MLP (one thread per edge), int32 indices
// ---------------------------------------------------------------------------
__global__ void __launch_bounds__(128) edge_kernel(
    const float* __restrict__ pcd,
    const float* __restrict__ also_pts,
    const int* __restrict__ also_labels,
    const int* __restrict__ row,
    const int* __restrict__ col,
    const float* __restrict__ w_in,
    const float* __restrict__ w1, const float* __restrict__ b1,
    const float* __restrict__ w2, const float* __restrict__ b2,
    const float* __restrict__ w_out, const float* __restrict__ b_out,
    float* __restrict__ out,
    int nE, int write_labels)
{
    __shared__ __align__(16) ull   s_w[2][2048];   // w1, w2 as f32x2
    __shared__ __align__(16) ull   s_b[2][32];     // b1, b2
    __shared__ __align__(16) ull   s_win3[96];     // w_in rows 64..66
    __shared__ __align__(16) ull   s_wout[64];     // w_out (64 x 2 f32)
    __shared__ float s_bout[2];

    for (int idx = threadIdx.x; idx < 2048; idx += 128) {
        s_w[0][idx] = ((const ull*)w1)[idx];
        s_w[1][idx] = ((const ull*)w2)[idx];
    }
    if (threadIdx.x < 32) {
        s_b[0][threadIdx.x] = ((const ull*)b1)[threadIdx.x];
        s_b[1][threadIdx.x] = ((const ull*)b2)[threadIdx.x];
    }
    for (int idx = threadIdx.x; idx < 96; idx += 128)
        s_win3[idx] = ((const ull*)(w_in + 64 * 64))[idx];
    if (threadIdx.x < 64)
        s_wout[threadIdx.x] = ((const ull*)w_out)[threadIdx.x];
    if (threadIdx.x < 2)
        s_bout[threadIdx.x] = b_out[threadIdx.x];
    __syncthreads();

    int e = blockIdx.x * 128 + threadIdx.x;
    if (e >= nE) return;

    int r = row[e];
    int c = col[e];

    float pos[3];
#pragma unroll
    for (int k = 0; k < 3; k++)
        pos[k] = also_pts[(size_t)r * 3 + k] - pcd[(size_t)c * 3 + k];

    // stage A: act = g[c] + pos @ w_in[64:67]   (b_in already folded into g)
    ull acc[32];
    const ull* gp = (const ull*)(g_buf + (size_t)c * 64);
#pragma unroll
    for (int j = 0; j < 32; j++) acc[j] = gp[j];

#pragma unroll
    for (int rr = 0; rr < 3; rr++) {
        ull a2 = bcast2(pos[rr]);
#pragma unroll
        for (int j = 0; j < 32; j += 2) {
            ulonglong2 w = *reinterpret_cast<const ulonglong2*>(&s_win3[rr * 32 + j]);
            acc[j]     = ffma2(a2, w.x, acc[j]);
            acc[j + 1] = ffma2(a2, w.y, acc[j + 1]);
        }
    }

    float act[64];
#pragma unroll
    for (int j = 0; j < 32; j++) unpack2(acc[j], act[2 * j], act[2 * j + 1]);

    // two hidden 64x64 layers (relu applied at consumption); L-loop kept
    // rolled to halve code size / I$ pressure
#pragma unroll 1
    for (int L = 0; L < 2; L++) {
        const ull* Ws = s_w[L];
        const ull* Bs = s_b[L];
#pragma unroll
        for (int j = 0; j < 32; j++) acc[j] = Bs[j];
#pragma unroll
        for (int i = 0; i < 64; i++) {
            ull a2 = bcast2(fmaxf(act[i], 0.0f));
#pragma unroll
            for (int j = 0; j < 32; j += 2) {
                ulonglong2 w = *reinterpret_cast<const ulonglong2*>(&Ws[i * 32 + j]);
                acc[j]     = ffma2(a2, w.x, acc[j]);
                acc[j + 1] = ffma2(a2, w.y, acc[j + 1]);
            }
        }
#pragma unroll
        for (int j = 0; j < 32; j++) unpack2(acc[j], act[2 * j], act[2 * j + 1]);
    }

    // fc_out (64 -> 2), two interleaved accumulator chains
    ull lacc0 = pack2(s_bout[0], s_bout[1]);
    ull lacc1 = pack2(0.0f, 0.0f);
#pragma unroll
    for (int i = 0; i < 64; i += 2) {
        lacc0 = ffma2(bcast2(act[i]),     s_wout[i],     lacc0);
        lacc1 = ffma2(bcast2(act[i + 1]), s_wout[i + 1], lacc1);
    }
    float l0a, l1a, l0b, l1b;
    unpack2(lacc0, l0a, l1a);
    unpack2(lacc1, l0b, l1b);
    float l0 = l0a + l0b;
    float l1 = l1a + l1b;

    float m  = fmaxf(l0, l1);
    float e0 = expf(l0 - m);
    float e1 = expf(l1 - m);
    float inv = 1.0f / (e0 + e1);

    out[2 * (size_t)e]     = e0 * inv;
    out[2 * (size_t)e + 1] = e1 * inv;
    if (write_labels)
        out[2 * (size_t)nE + e] = (float)also_labels[r];
}

// ---------------------------------------------------------------------------
extern "C" void kernel_launch(void* const* d_in, const int* in_sizes, int n_in,
                              void* d_out, int out_size)
{
    const float* pcd         = (const float*)d_in[0];
    const float* feats       = (const float*)d_in[1];
    const float* also_pts    = (const float*)d_in[2];
    const int*   also_labels = (const int*)d_in[3];
    const int*   row         = (const int*)d_in[4];
    const int*   col         = (const int*)d_in[5];
    const float* w_in        = (const float*)d_in[6];
    const float* b_in        = (const float*)d_in[7];
    const float* w1          = (const float*)d_in[8];
    const float* b1          = (const float*)d_in[9];
    const float* w2          = (const float*)d_in[10];
    const float* b2          = (const float*)d_in[11];
    const float* w_out       = (const float*)d_in[12];
    const float* b_out       = (const float*)d_in[13];

    int nPts = in_sizes[1] / 64;
    if (nPts > 100000) nPts = 100000;
    int nE = in_sizes[4];

    // output layout: [probs (2E floats) | labels-as-float (E floats)] if room
    int write_labels = ((long long)out_size >= 3LL * nE) ? 1 : 0;

    precompute_kernel<<<(nPts + 127) / 128, 128>>>(feats, w_in, b_in, nPts);

    int grid = (nE + 127) / 128;
    edge_kernel<<<grid, 128>>>(pcd, also_pts, also_labels, row, col,
                               w_in, w1, b1, w2, b2, w_out, b_out,
                               (float*)d_out, nE, write_labels);
}

// round 4
// speedup vs baseline: 2.6717x; 2.6717x over previous
#include <cuda_runtime.h>
#include <cuda_bf16.h>
#include <cstdint>

typedef unsigned long long ull;

// Precomputed g = feats @ w_in[0:64,:] + b_in  (N x 64)
__device__ float g_buf[100000 * 64];
// Packed bf16 weight splits: [w1hi, w1lo, w2hi, w2lo], each 64x64 bf16 = 2048 u32
__device__ uint32_t w_pack[4][2048];

// ---------------------------------------------------------------------------
// helpers
// ---------------------------------------------------------------------------
__device__ __forceinline__ ull pack2(float lo, float hi) {
    ull r; asm("mov.b64 %0, {%1, %2};" : "=l"(r) : "f"(lo), "f"(hi)); return r;
}
__device__ __forceinline__ ull bcast2(float v) { return pack2(v, v); }
__device__ __forceinline__ ull ffma2(ull a, ull b, ull c) {
    ull d; asm("fma.rn.f32x2 %0, %1, %2, %3;" : "=l"(d) : "l"(a), "l"(b), "l"(c)); return d;
}
__device__ __forceinline__ uint32_t smem_u32(const void* p) {
    uint32_t a;
    asm("{ .reg .u64 t; cvta.to.shared.u64 t, %1; cvt.u32.u64 %0, t; }" : "=r"(a) : "l"(p));
    return a;
}
// pack two f32 -> bf16x2 (arg0 = low half, arg1 = high half)
__device__ __forceinline__ uint32_t pack_bf16x2(float lo, float hi) {
    uint32_t d;
    asm("cvt.rn.bf16x2.f32 %0, %1, %2;" : "=r"(d) : "f"(hi), "f"(lo));
    return d;
}
__device__ __forceinline__ void ldsm_x4(uint32_t* r, uint32_t addr) {
    asm volatile("ldmatrix.sync.aligned.m8n8.x4.shared.b16 {%0,%1,%2,%3}, [%4];"
                 : "=r"(r[0]), "=r"(r[1]), "=r"(r[2]), "=r"(r[3]) : "r"(addr));
}
__device__ __forceinline__ void ldsm_x4_t(uint32_t* r, uint32_t addr) {
    asm volatile("ldmatrix.sync.aligned.m8n8.x4.trans.shared.b16 {%0,%1,%2,%3}, [%4];"
                 : "=r"(r[0]), "=r"(r[1]), "=r"(r[2]), "=r"(r[3]) : "r"(addr));
}
__device__ __forceinline__ void mma16816(float* c, const uint32_t* a, const uint32_t* b) {
    asm volatile(
        "mma.sync.aligned.m16n8k16.row.col.f32.bf16.bf16.f32 "
        "{%0,%1,%2,%3}, {%4,%5,%6,%7}, {%8,%9}, {%0,%1,%2,%3};"
        : "+f"(c[0]), "+f"(c[1]), "+f"(c[2]), "+f"(c[3])
        : "r"(a[0]), "r"(a[1]), "r"(a[2]), "r"(a[3]), "r"(b[0]), "r"(b[1]));
}

// ---------------------------------------------------------------------------
// Kernel 0: split w1/w2 into bf16 hi/lo packed pairs
// ---------------------------------------------------------------------------
__global__ void __launch_bounds__(128) convert_weights(
    const float* __restrict__ w1, const float* __restrict__ w2)
{
    int idx = blockIdx.x * 128 + threadIdx.x;   // 0..2047 (pair index)
    if (idx >= 2048) return;
    float v0 = w1[2 * idx], v1 = w1[2 * idx + 1];
    uint32_t hp = pack_bf16x2(v0, v1);
    float h0 = __uint_as_float(hp << 16), h1 = __uint_as_float(hp & 0xFFFF0000u);
    w_pack[0][idx] = hp;
    w_pack[1][idx] = pack_bf16x2(v0 - h0, v1 - h1);
    v0 = w2[2 * idx]; v1 = w2[2 * idx + 1];
    hp = pack_bf16x2(v0, v1);
    h0 = __uint_as_float(hp << 16); h1 = __uint_as_float(hp & 0xFFFF0000u);
    w_pack[2][idx] = hp;
    w_pack[3][idx] = pack_bf16x2(v0 - h0, v1 - h1);
}

// ---------------------------------------------------------------------------
// Kernel 1: g[n,:] = feats[n,:] @ w_in[0:64,:] + b_in
// ---------------------------------------------------------------------------
__global__ void __launch_bounds__(128) precompute_kernel(
    const float* __restrict__ feats, const float* __restrict__ w_in,
    const float* __restrict__ b_in, int n_pts)
{
    __shared__ __align__(16) ull s_w[2048];
    for (int idx = threadIdx.x; idx < 2048; idx += 128)
        s_w[idx] = ((const ull*)w_in)[idx];
    __syncthreads();

    int n = blockIdx.x * 128 + threadIdx.x;
    if (n >= n_pts) return;

    float act[64];
    const float4* fp = (const float4*)(feats + (size_t)n * 64);
#pragma unroll
    for (int i = 0; i < 16; i++) {
        float4 v = fp[i];
        act[4 * i] = v.x; act[4 * i + 1] = v.y; act[4 * i + 2] = v.z; act[4 * i + 3] = v.w;
    }
    ull acc[32];
    const ull* bp = (const ull*)b_in;
#pragma unroll
    for (int j = 0; j < 32; j++) acc[j] = bp[j];
#pragma unroll
    for (int i = 0; i < 64; i++) {
        ull a2 = bcast2(act[i]);
#pragma unroll
        for (int j = 0; j < 32; j += 2) {
            ulonglong2 w = *reinterpret_cast<const ulonglong2*>(&s_w[i * 32 + j]);
            acc[j] = ffma2(a2, w.x, acc[j]);
            acc[j + 1] = ffma2(a2, w.y, acc[j + 1]);
        }
    }
    ull* gp = (ull*)(g_buf + (size_t)n * 64);
#pragma unroll
    for (int j = 0; j < 32; j++) gp[j] = acc[j];
}

// ---------------------------------------------------------------------------
// Kernel 2: persistent mma.sync edge MLP. 128 edges/tile, 4 warps, 32 edges/warp.
// SMEM layout (bytes):
//   [0)      4 weight tiles [64 rows][72 bf16] (144B stride): hi1, lo1, hi2, lo2
//   [36864)  A_hi tile [128][72] bf16
//   [55296)  A_lo tile [128][72] bf16
//   [73728)  w3 (3x64 f32), [74496) w_out (64x2 f32), [75008) b1, [75264) b2, [75520) b_out
// ---------------------------------------------------------------------------
#define SM_W     0
#define SM_AHI   36864
#define SM_ALO   55296
#define SM_W3    73728
#define SM_WOUT  74496
#define SM_B1    75008
#define SM_B2    75264
#define SM_BOUT  75520
#define SM_TOTAL 75552

__global__ void __launch_bounds__(128) edge_mma_kernel(
    const float* __restrict__ pcd,
    const float* __restrict__ also_pts,
    const int* __restrict__ also_labels,
    const int* __restrict__ row,
    const int* __restrict__ col,
    const float* __restrict__ w_in,
    const float* __restrict__ b1g,
    const float* __restrict__ b2g,
    const float* __restrict__ w_outg, const float* __restrict__ b_outg,
    float* __restrict__ out,
    int nE, int nTiles, int write_labels)
{
    extern __shared__ __align__(16) char smem[];
    const int tid = threadIdx.x;
    const int lane = tid & 31;
    const int warp = tid >> 5;

    // ---- stage weights into SMEM (144B row stride, conflict-free ldsm) ----
#pragma unroll
    for (int m = 0; m < 4; m++) {
        for (int idx = tid; idx < 2048; idx += 128) {
            int rk = idx >> 5, cc = idx & 31;
            *(uint32_t*)(smem + SM_W + m * 9216 + rk * 144 + cc * 4) = w_pack[m][idx];
        }
    }
    float* s_w3 = (float*)(smem + SM_W3);
    float* s_wout = (float*)(smem + SM_WOUT);
    float* s_b1 = (float*)(smem + SM_B1);
    float* s_b2 = (float*)(smem + SM_B2);
    float* s_bout = (float*)(smem + SM_BOUT);
    for (int idx = tid; idx < 192; idx += 128) s_w3[idx] = w_in[64 * 64 + idx];
    if (tid < 128) s_wout[tid] = w_outg[tid];
    if (tid < 64) { s_b1[tid] = b1g[tid]; s_b2[tid] = b2g[tid]; }
    if (tid < 2) s_bout[tid] = b_outg[tid];
    __syncthreads();

    const uint32_t sbase = smem_u32(smem);
    const uint32_t sAhi = sbase + SM_AHI;
    const uint32_t sAlo = sbase + SM_ALO;

    // per-lane ldmatrix address components
    const int a_row = (lane & 7) + ((lane >> 3) & 1) * 8;      // 0..15
    const int a_c8 = ((lane >> 4) & 1) * 8;                     // 0 / +8 cols
    const int b_row = (lane & 7) + ((lane >> 3) & 3) * 8;       // 0..31

    for (int tile = blockIdx.x; tile < nTiles; tile += gridDim.x) {
        const int e = tile * 128 + tid;
        const bool valid = e < nE;
        const int ee = valid ? e : nE - 1;
        const int r = row[ee];
        const int c = col[ee];

        const float p0 = also_pts[(size_t)r * 3 + 0] - pcd[(size_t)c * 3 + 0];
        const float p1 = also_pts[(size_t)r * 3 + 1] - pcd[(size_t)c * 3 + 1];
        const float p2 = also_pts[(size_t)r * 3 + 2] - pcd[(size_t)c * 3 + 2];

        // ---- stage A: a = relu(g[c] + pos @ w3); hi/lo split -> SMEM ----
        {
            const float4* gp = (const float4*)(g_buf + (size_t)c * 64);
            float a[64];
#pragma unroll
            for (int q = 0; q < 16; q++) {
                float4 v = gp[q];
                a[4 * q] = v.x; a[4 * q + 1] = v.y; a[4 * q + 2] = v.z; a[4 * q + 3] = v.w;
            }
#pragma unroll
            for (int j = 0; j < 64; j++)
                a[j] = fmaf(p0, s_w3[j], fmaf(p1, s_w3[64 + j], fmaf(p2, s_w3[128 + j], a[j])));

            const uint32_t rbase_hi = sAhi + tid * 144;
            const uint32_t rbase_lo = sAlo + tid * 144;
#pragma unroll
            for (int q = 0; q < 8; q++) {
                uint32_t h4[4], l4[4];
#pragma unroll
                for (int p = 0; p < 4; p++) {
                    float r0 = fmaxf(a[8 * q + 2 * p], 0.0f);
                    float r1 = fmaxf(a[8 * q + 2 * p + 1], 0.0f);
                    uint32_t hp = pack_bf16x2(r0, r1);
                    float h0 = __uint_as_float(hp << 16);
                    float h1 = __uint_as_float(hp & 0xFFFF0000u);
                    h4[p] = hp;
                    l4[p] = pack_bf16x2(r0 - h0, r1 - h1);
                }
                asm volatile("st.shared.v4.b32 [%0], {%1,%2,%3,%4};" ::
                             "r"(rbase_hi + q * 16), "r"(h4[0]), "r"(h4[1]), "r"(h4[2]), "r"(h4[3]));
                asm volatile("st.shared.v4.b32 [%0], {%1,%2,%3,%4};" ::
                             "r"(rbase_lo + q * 16), "r"(l4[0]), "r"(l4[1]), "r"(l4[2]), "r"(l4[3]));
            }
        }
        __syncwarp();

        // ---- load A fragments (layer 1) ----
        uint32_t Ahi[2][4][4], Alo[2][4][4];
#pragma unroll
        for (int mt = 0; mt < 2; mt++) {
            const int rowm = warp * 32 + mt * 16 + a_row;
#pragma unroll
            for (int kt = 0; kt < 4; kt++) {
                uint32_t off = (uint32_t)rowm * 144 + (kt * 16 + a_c8) * 2;
                ldsm_x4(Ahi[mt][kt], sAhi + off);
                ldsm_x4(Alo[mt][kt], sAlo + off);
            }
        }

        float C[2][8][4];

        // ===================== two hidden layers =====================
#pragma unroll
        for (int L = 0; L < 2; L++) {
#pragma unroll
            for (int mt = 0; mt < 2; mt++)
#pragma unroll
                for (int nt = 0; nt < 8; nt++)
#pragma unroll
                    for (int i = 0; i < 4; i++) C[mt][nt][i] = 0.0f;

            const uint32_t wbase_hi = sbase + SM_W + L * 18432;
            const uint32_t wbase_lo = wbase_hi + 9216;
#pragma unroll
            for (int kg = 0; kg < 2; kg++) {
#pragma unroll
                for (int nt = 0; nt < 8; nt++) {
                    uint32_t off = (uint32_t)(kg * 32 + b_row) * 144 + nt * 16;
                    uint32_t Bhi[4], Blo[4];
                    ldsm_x4_t(Bhi, wbase_hi + off);
                    ldsm_x4_t(Blo, wbase_lo + off);
#pragma unroll
                    for (int mt = 0; mt < 2; mt++) {
                        mma16816(C[mt][nt], Ahi[mt][2 * kg], Bhi);
                        mma16816(C[mt][nt], Ahi[mt][2 * kg], Blo);
                        mma16816(C[mt][nt], Alo[mt][2 * kg], Bhi);
                        mma16816(C[mt][nt], Ahi[mt][2 * kg + 1], Bhi + 2);
                        mma16816(C[mt][nt], Ahi[mt][2 * kg + 1], Blo + 2);
                        mma16816(C[mt][nt], Alo[mt][2 * kg + 1], Bhi + 2);
                    }
                }
            }

            if (L == 0) {
                // epilogue 1: x = relu(C + b1) -> new A fragments (in registers)
#pragma unroll
                for (int mt = 0; mt < 2; mt++) {
#pragma unroll
                    for (int kt = 0; kt < 4; kt++) {
#pragma unroll
                        for (int half = 0; half < 2; half++) {
                            const int nt = 2 * kt + half;
                            const int col0 = nt * 8 + (lane & 3) * 2;
                            float2 bb = *(const float2*)(s_b1 + col0);
                            float x0 = fmaxf(C[mt][nt][0] + bb.x, 0.0f);
                            float x1 = fmaxf(C[mt][nt][1] + bb.y, 0.0f);
                            float x2 = fmaxf(C[mt][nt][2] + bb.x, 0.0f);
                            float x3 = fmaxf(C[mt][nt][3] + bb.y, 0.0f);
                            uint32_t hp0 = pack_bf16x2(x0, x1);
                            uint32_t hp1 = pack_bf16x2(x2, x3);
                            Ahi[mt][kt][2 * half + 0] = hp0;
                            Ahi[mt][kt][2 * half + 1] = hp1;
                            Alo[mt][kt][2 * half + 0] = pack_bf16x2(
                                x0 - __uint_as_float(hp0 << 16),
                                x1 - __uint_as_float(hp0 & 0xFFFF0000u));
                            Alo[mt][kt][2 * half + 1] = pack_bf16x2(
                                x2 - __uint_as_float(hp1 << 16),
                                x3 - __uint_as_float(hp1 & 0xFFFF0000u));
                        }
                    }
                }
            }
        }

        // ---- final epilogue: logits = (C + b2) @ w_out + b_out; softmax ----
#pragma unroll
        for (int mt = 0; mt < 2; mt++) {
            float l0a = 0.0f, l1a = 0.0f, l0b = 0.0f, l1b = 0.0f;
#pragma unroll
            for (int nt = 0; nt < 8; nt++) {
                const int col0 = nt * 8 + (lane & 3) * 2;
                float2 bb = *(const float2*)(s_b2 + col0);
                float4 wo = *(const float4*)(s_wout + 2 * col0);
                float x0 = C[mt][nt][0] + bb.x;
                float x1 = C[mt][nt][1] + bb.y;
                float x2 = C[mt][nt][2] + bb.x;
                float x3 = C[mt][nt][3] + bb.y;
                l0a = fmaf(x0, wo.x, fmaf(x1, wo.z, l0a));
                l1a = fmaf(x0, wo.y, fmaf(x1, wo.w, l1a));
                l0b = fmaf(x2, wo.x, fmaf(x3, wo.z, l0b));
                l1b = fmaf(x2, wo.y, fmaf(x3, wo.w, l1b));
            }
#pragma unroll
            for (int off = 1; off <= 2; off <<= 1) {
                l0a += __shfl_xor_sync(0xFFFFFFFFu, l0a, off);
                l1a += __shfl_xor_sync(0xFFFFFFFFu, l1a, off);
                l0b += __shfl_xor_sync(0xFFFFFFFFu, l0b, off);
                l1b += __shfl_xor_sync(0xFFFFFFFFu, l1b, off);
            }
            if ((lane & 3) == 0) {
                const int e0 = tile * 128 + warp * 32 + mt * 16 + (lane >> 2);
                float la0 = l0a + s_bout[0], la1 = l1a + s_bout[1];
                float m0 = fmaxf(la0, la1);
                float ea = expf(la0 - m0), eb = expf(la1 - m0);
                float inv = 1.0f / (ea + eb);
                if (e0 < nE)
                    *(float2*)(out + 2 * (size_t)e0) = make_float2(ea * inv, eb * inv);

                const int e1 = e0 + 8;
                float lb0 = l0b + s_bout[0], lb1 = l1b + s_bout[1];
                float m1 = fmaxf(lb0, lb1);
                float ec = expf(lb0 - m1), ed = expf(lb1 - m1);
                float inv2 = 1.0f / (ec + ed);
                if (e1 < nE)
                    *(float2*)(out + 2 * (size_t)e1) = make_float2(ec * inv2, ed * inv2);
            }
        }

        if (write_labels && valid)
            out[2 * (size_t)nE + e] = (float)also_labels[r];
        __syncwarp();   // A-tile rows reused next iteration by this warp only
    }
}

// ---------------------------------------------------------------------------
extern "C" void kernel_launch(void* const* d_in, const int* in_sizes, int n_in,
                              void* d_out, int out_size)
{
    const float* pcd         = (const float*)d_in[0];
    const float* feats       = (const float*)d_in[1];
    const float* also_pts    = (const float*)d_in[2];
    const int*   also_labels = (const int*)d_in[3];
    const int*   row         = (const int*)d_in[4];
    const int*   col         = (const int*)d_in[5];
    const float* w_in        = (const float*)d_in[6];
    const float* b_in        = (const float*)d_in[7];
    const float* w1          = (const float*)d_in[8];
    const float* b1          = (const float*)d_in[9];
    const float* w2          = (const float*)d_in[10];
    const float* b2          = (const float*)d_in[11];
    const float* w_out       = (const float*)d_in[12];
    const float* b_out       = (const float*)d_in[13];

    int nPts = in_sizes[1] / 64;
    if (nPts > 100000) nPts = 100000;
    int nE = in_sizes[4];
    int nTiles = (nE + 127) / 128;
    int write_labels = ((long long)out_size >= 3LL * nE) ? 1 : 0;

    static int attr_done = 0;
    if (!attr_done) {
        cudaFuncSetAttribute(edge_mma_kernel,
                             cudaFuncAttributeMaxDynamicSharedMemorySize, SM_TOTAL);
        attr_done = 1;
    }

    convert_weights<<<16, 128>>>(w1, w2);
    precompute_kernel<<<(nPts + 127) / 128, 128>>>(feats, w_in, b_in, nPts);

    int grid = 148 * 3;
    if (grid > nTiles) grid = nTiles;
    edge_mma_kernel<<<grid, 128, SM_TOTAL>>>(pcd, also_pts, also_labels, row, col,
                                             w_in, b1, b2, w_out, b_out,
                                             (float*)d_out, nE, nTiles, write_labels);
}

// round 5
// speedup vs baseline: 3.9080x; 1.4628x over previous
#include <cuda_runtime.h>
#include <cuda_fp16.h>
#include <cstdint>

typedef unsigned long long ull;

// Precomputed g = feats @ w_in[0:64,:] + b_in  (N x 64)
__device__ float g_buf[100000 * 64];
// Packed fp16 weight splits: [w1hi, w1lo, w2hi, w2lo], each 64x64 fp16 = 2048 u32
__device__ uint32_t w_pack[4][2048];

// ---------------------------------------------------------------------------
// helpers
// ---------------------------------------------------------------------------
__device__ __forceinline__ ull pack2(float lo, float hi) {
    ull r; asm("mov.b64 %0, {%1, %2};" : "=l"(r) : "f"(lo), "f"(hi)); return r;
}
__device__ __forceinline__ ull bcast2(float v) { return pack2(v, v); }
__device__ __forceinline__ ull ffma2(ull a, ull b, ull c) {
    ull d; asm("fma.rn.f32x2 %0, %1, %2, %3;" : "=l"(d) : "l"(a), "l"(b), "l"(c)); return d;
}
__device__ __forceinline__ uint32_t smem_u32(const void* p) {
    uint32_t a;
    asm("{ .reg .u64 t; cvta.to.shared.u64 t, %1; cvt.u32.u64 %0, t; }" : "=r"(a) : "l"(p));
    return a;
}
__device__ __forceinline__ uint32_t pack_f16x2(float lo, float hi) {
    __half2 h = __floats2half2_rn(lo, hi);      // lo -> low half
    return *reinterpret_cast<uint32_t*>(&h);
}
__device__ __forceinline__ void ldsm_x4(uint32_t* r, uint32_t addr) {
    asm volatile("ldmatrix.sync.aligned.m8n8.x4.shared.b16 {%0,%1,%2,%3}, [%4];"
                 : "=r"(r[0]), "=r"(r[1]), "=r"(r[2]), "=r"(r[3]) : "r"(addr));
}
__device__ __forceinline__ void ldsm_x4_t(uint32_t* r, uint32_t addr) {
    asm volatile("ldmatrix.sync.aligned.m8n8.x4.trans.shared.b16 {%0,%1,%2,%3}, [%4];"
                 : "=r"(r[0]), "=r"(r[1]), "=r"(r[2]), "=r"(r[3]) : "r"(addr));
}
__device__ __forceinline__ void mma16816(float* c, const uint32_t* a, const uint32_t* b) {
    asm volatile(
        "mma.sync.aligned.m16n8k16.row.col.f32.f16.f16.f32 "
        "{%0,%1,%2,%3}, {%4,%5,%6,%7}, {%8,%9}, {%0,%1,%2,%3};"
        : "+f"(c[0]), "+f"(c[1]), "+f"(c[2]), "+f"(c[3])
        : "r"(a[0]), "r"(a[1]), "r"(a[2]), "r"(a[3]), "r"(b[0]), "r"(b[1]));
}

// ---------------------------------------------------------------------------
// Kernel 1: fused  (a) g[n,:] = feats[n,:] @ w_in[0:64,:] + b_in
//                  (b) last 16 blocks: fp16 hi/lo split of w1, w2
// ---------------------------------------------------------------------------
__global__ void __launch_bounds__(128) precompute_kernel(
    const float* __restrict__ feats, const float* __restrict__ w_in,
    const float* __restrict__ b_in, int n_pts,
    const float* __restrict__ w1g, const float* __restrict__ w2g)
{
    if (blockIdx.x >= gridDim.x - 16) {
        int idx = (blockIdx.x - (gridDim.x - 16)) * 128 + threadIdx.x;  // 0..2047
        float v0 = w1g[2 * idx], v1 = w1g[2 * idx + 1];
        __half h0 = __float2half_rn(v0), h1 = __float2half_rn(v1);
        w_pack[0][idx] = pack_f16x2(__half2float(h0), 0.0f) | (pack_f16x2(__half2float(h1), 0.0f) << 16);
        w_pack[0][idx] = (uint32_t)*reinterpret_cast<unsigned short*>(&h0)
                       | ((uint32_t)*reinterpret_cast<unsigned short*>(&h1) << 16);
        w_pack[1][idx] = pack_f16x2(v0 - __half2float(h0), v1 - __half2float(h1));
        v0 = w2g[2 * idx]; v1 = w2g[2 * idx + 1];
        h0 = __float2half_rn(v0); h1 = __float2half_rn(v1);
        w_pack[2][idx] = (uint32_t)*reinterpret_cast<unsigned short*>(&h0)
                       | ((uint32_t)*reinterpret_cast<unsigned short*>(&h1) << 16);
        w_pack[3][idx] = pack_f16x2(v0 - __half2float(h0), v1 - __half2float(h1));
        return;
    }

    __shared__ __align__(16) ull s_w[2048];
    for (int idx = threadIdx.x; idx < 2048; idx += 128)
        s_w[idx] = ((const ull*)w_in)[idx];
    __syncthreads();

    int n = blockIdx.x * 128 + threadIdx.x;
    if (n >= n_pts) return;

    float act[64];
    const float4* fp = (const float4*)(feats + (size_t)n * 64);
#pragma unroll
    for (int i = 0; i < 16; i++) {
        float4 v = fp[i];
        act[4 * i] = v.x; act[4 * i + 1] = v.y; act[4 * i + 2] = v.z; act[4 * i + 3] = v.w;
    }
    ull acc[32];
    const ull* bp = (const ull*)b_in;
#pragma unroll
    for (int j = 0; j < 32; j++) acc[j] = bp[j];
#pragma unroll
    for (int i = 0; i < 64; i++) {
        ull a2 = bcast2(act[i]);
#pragma unroll
        for (int j = 0; j < 32; j += 2) {
            ulonglong2 w = *reinterpret_cast<const ulonglong2*>(&s_w[i * 32 + j]);
            acc[j] = ffma2(a2, w.x, acc[j]);
            acc[j + 1] = ffma2(a2, w.y, acc[j + 1]);
        }
    }
    ull* gp = (ull*)(g_buf + (size_t)n * 64);
#pragma unroll
    for (int j = 0; j < 32; j++) gp[j] = acc[j];
}

// ---------------------------------------------------------------------------
// Kernel 2: persistent mma.sync edge MLP (fp16, 2-term W split).
// 128 edges/tile, 4 warps, 32 edges/warp.
// SMEM (bytes):
//   [0)      4 weight tiles [64][72 fp16] (144B stride): hi1, lo1, hi2, lo2
//   [36864)  A tile [128][72] fp16
//   [55296)  w3 (3x64 f32), [56064) w_out, [56576) b1, [56832) b2, [57088) b_out
// ---------------------------------------------------------------------------
#define SM_W     0
#define SM_A     36864
#define SM_W3    55296
#define SM_WOUT  56064
#define SM_B1    56576
#define SM_B2    56832
#define SM_BOUT  57088
#define SM_TOTAL 57344

__global__ void __launch_bounds__(128, 3) edge_mma_kernel(
    const float* __restrict__ pcd,
    const float* __restrict__ also_pts,
    const int* __restrict__ also_labels,
    const int* __restrict__ row,
    const int* __restrict__ col,
    const float* __restrict__ w_in,
    const float* __restrict__ b1g,
    const float* __restrict__ b2g,
    const float* __restrict__ w_outg, const float* __restrict__ b_outg,
    float* __restrict__ out,
    int nE, int nTiles, int write_labels)
{
    extern __shared__ __align__(16) char smem[];
    const int tid = threadIdx.x;
    const int lane = tid & 31;
    const int warp = tid >> 5;

    // ---- stage weights into SMEM (144B row stride, conflict-free ldsm) ----
#pragma unroll
    for (int m = 0; m < 4; m++) {
        for (int idx = tid; idx < 2048; idx += 128) {
            int rk = idx >> 5, cc = idx & 31;
            *(uint32_t*)(smem + SM_W + m * 9216 + rk * 144 + cc * 4) = w_pack[m][idx];
        }
    }
    float* s_w3 = (float*)(smem + SM_W3);
    float* s_wout = (float*)(smem + SM_WOUT);
    float* s_b1 = (float*)(smem + SM_B1);
    float* s_b2 = (float*)(smem + SM_B2);
    float* s_bout = (float*)(smem + SM_BOUT);
    for (int idx = tid; idx < 192; idx += 128) s_w3[idx] = w_in[64 * 64 + idx];
    if (tid < 128) s_wout[tid] = w_outg[tid];
    if (tid < 64) { s_b1[tid] = b1g[tid]; s_b2[tid] = b2g[tid]; }
    if (tid < 2) s_bout[tid] = b_outg[tid];
    __syncthreads();

    const uint32_t sbase = smem_u32(smem);
    const uint32_t sA = sbase + SM_A;

    const int a_row = (lane & 7) + ((lane >> 3) & 1) * 8;      // 0..15
    const int a_c8 = ((lane >> 4) & 1) * 8;                     // 0 / +8 cols
    const int b_row = (lane & 7) + ((lane >> 3) & 3) * 8;       // 0..31

    // preload first tile's indices
    int r = 0, c = 0;
    if (blockIdx.x < nTiles) {
        int e0 = blockIdx.x * 128 + tid;
        int ee = e0 < nE ? e0 : nE - 1;
        r = row[ee]; c = col[ee];
    }

    for (int tile = blockIdx.x; tile < nTiles; tile += gridDim.x) {
        const int e = tile * 128 + tid;
        const bool valid = e < nE;

        // ---- prefetch next tile's indices + g row (hides gather chain) ----
        int rn = r, cn = c;
        {
            int tn = tile + gridDim.x;
            if (tn < nTiles) {
                int en = tn * 128 + tid;
                int een = en < nE ? en : nE - 1;
                rn = row[een]; cn = col[een];
                const char* gp_n = (const char*)(g_buf + (size_t)cn * 64);
                asm volatile("prefetch.global.L1 [%0];" :: "l"(gp_n));
                asm volatile("prefetch.global.L1 [%0];" :: "l"(gp_n + 128));
                asm volatile("prefetch.global.L1 [%0];" :: "l"(also_pts + (size_t)rn * 3));
                asm volatile("prefetch.global.L1 [%0];" :: "l"(pcd + (size_t)cn * 3));
            }
        }

        const float p0 = also_pts[(size_t)r * 3 + 0] - pcd[(size_t)c * 3 + 0];
        const float p1 = also_pts[(size_t)r * 3 + 1] - pcd[(size_t)c * 3 + 1];
        const float p2 = also_pts[(size_t)r * 3 + 2] - pcd[(size_t)c * 3 + 2];

        // ---- stage A: a = relu(g[c] + pos @ w3) -> fp16 SMEM tile ----
        {
            const float4* gp = (const float4*)(g_buf + (size_t)c * 64);
            float a[64];
#pragma unroll
            for (int q = 0; q < 16; q++) {
                float4 v = gp[q];
                a[4 * q] = v.x; a[4 * q + 1] = v.y; a[4 * q + 2] = v.z; a[4 * q + 3] = v.w;
            }
#pragma unroll
            for (int j = 0; j < 64; j++)
                a[j] = fmaf(p0, s_w3[j], fmaf(p1, s_w3[64 + j], fmaf(p2, s_w3[128 + j], a[j])));

            const uint32_t rbase = sA + tid * 144;
#pragma unroll
            for (int q = 0; q < 8; q++) {
                uint32_t h4[4];
#pragma unroll
                for (int p = 0; p < 4; p++)
                    h4[p] = pack_f16x2(fmaxf(a[8 * q + 2 * p], 0.0f),
                                       fmaxf(a[8 * q + 2 * p + 1], 0.0f));
                asm volatile("st.shared.v4.b32 [%0], {%1,%2,%3,%4};" ::
                             "r"(rbase + q * 16), "r"(h4[0]), "r"(h4[1]), "r"(h4[2]), "r"(h4[3]));
            }
        }
        __syncwarp();

        // ---- load A fragments (layer 1) ----
        uint32_t A[2][4][4];
#pragma unroll
        for (int mt = 0; mt < 2; mt++) {
            const int rowm = warp * 32 + mt * 16 + a_row;
#pragma unroll
            for (int kt = 0; kt < 4; kt++)
                ldsm_x4(A[mt][kt], sA + (uint32_t)rowm * 144 + (kt * 16 + a_c8) * 2);
        }

        float C[2][8][4];

        // ===================== two hidden layers =====================
#pragma unroll
        for (int L = 0; L < 2; L++) {
#pragma unroll
            for (int mt = 0; mt < 2; mt++)
#pragma unroll
                for (int nt = 0; nt < 8; nt++)
#pragma unroll
                    for (int i = 0; i < 4; i++) C[mt][nt][i] = 0.0f;

            const uint32_t wbase_hi = sbase + SM_W + L * 18432;
            const uint32_t wbase_lo = wbase_hi + 9216;
#pragma unroll
            for (int kg = 0; kg < 2; kg++) {
#pragma unroll
                for (int nt = 0; nt < 8; nt++) {
                    uint32_t off = (uint32_t)(kg * 32 + b_row) * 144 + nt * 16;
                    uint32_t Bhi[4], Blo[4];
                    ldsm_x4_t(Bhi, wbase_hi + off);
                    ldsm_x4_t(Blo, wbase_lo + off);
#pragma unroll
                    for (int mt = 0; mt < 2; mt++) {
                        mma16816(C[mt][nt], A[mt][2 * kg], Bhi);
                        mma16816(C[mt][nt], A[mt][2 * kg], Blo);
                        mma16816(C[mt][nt], A[mt][2 * kg + 1], Bhi + 2);
                        mma16816(C[mt][nt], A[mt][2 * kg + 1], Blo + 2);
                    }
                }
            }

            if (L == 0) {
                // epilogue 1: x = relu(C + b1) -> new A fragments in registers
#pragma unroll
                for (int mt = 0; mt < 2; mt++) {
#pragma unroll
                    for (int kt = 0; kt < 4; kt++) {
#pragma unroll
                        for (int half = 0; half < 2; half++) {
                            const int nt = 2 * kt + half;
                            const int col0 = nt * 8 + (lane & 3) * 2;
                            float2 bb = *(const float2*)(s_b1 + col0);
                            A[mt][kt][2 * half + 0] =
                                pack_f16x2(fmaxf(C[mt][nt][0] + bb.x, 0.0f),
                                           fmaxf(C[mt][nt][1] + bb.y, 0.0f));
                            A[mt][kt][2 * half + 1] =
                                pack_f16x2(fmaxf(C[mt][nt][2] + bb.x, 0.0f),
                                           fmaxf(C[mt][nt][3] + bb.y, 0.0f));
                        }
                    }
                }
            }
        }

        // ---- final epilogue: logits = (C + b2) @ w_out + b_out; softmax ----
#pragma unroll
        for (int mt = 0; mt < 2; mt++) {
            float l0a = 0.0f, l1a = 0.0f, l0b = 0.0f, l1b = 0.0f;
#pragma unroll
            for (int nt = 0; nt < 8; nt++) {
                const int col0 = nt * 8 + (lane & 3) * 2;
                float2 bb = *(const float2*)(s_b2 + col0);
                float4 wo = *(const float4*)(s_wout + 2 * col0);
                float x0 = C[mt][nt][0] + bb.x;
                float x1 = C[mt][nt][1] + bb.y;
                float x2 = C[mt][nt][2] + bb.x;
                float x3 = C[mt][nt][3] + bb.y;
                l0a = fmaf(x0, wo.x, fmaf(x1, wo.z, l0a));
                l1a = fmaf(x0, wo.y, fmaf(x1, wo.w, l1a));
                l0b = fmaf(x2, wo.x, fmaf(x3, wo.z, l0b));
                l1b = fmaf(x2, wo.y, fmaf(x3, wo.w, l1b));
            }
#pragma unroll
            for (int off = 1; off <= 2; off <<= 1) {
                l0a += __shfl_xor_sync(0xFFFFFFFFu, l0a, off);
                l1a += __shfl_xor_sync(0xFFFFFFFFu, l1a, off);
                l0b += __shfl_xor_sync(0xFFFFFFFFu, l0b, off);
                l1b += __shfl_xor_sync(0xFFFFFFFFu, l1b, off);
            }
            if ((lane & 3) == 0) {
                const int e0 = tile * 128 + warp * 32 + mt * 16 + (lane >> 2);
                float la0 = l0a + s_bout[0], la1 = l1a + s_bout[1];
                float m0 = fmaxf(la0, la1);
                float ea = expf(la0 - m0), eb = expf(la1 - m0);
                float inv = 1.0f / (ea + eb);
                if (e0 < nE)
                    *(float2*)(out + 2 * (size_t)e0) = make_float2(ea * inv, eb * inv);

                const int e1 = e0 + 8;
                float lb0 = l0b + s_bout[0], lb1 = l1b + s_bout[1];
                float m1 = fmaxf(lb0, lb1);
                float ec = expf(lb0 - m1), ed = expf(lb1 - m1);
                float inv2 = 1.0f / (ec + ed);
                if (e1 < nE)
                    *(float2*)(out + 2 * (size_t)e1) = make_float2(ec * inv2, ed * inv2);
            }
        }

        if (write_labels && valid)
            out[2 * (size_t)nE + e] = (float)also_labels[r];

        r = rn; c = cn;
        __syncwarp();   // A-tile rows reused next iteration by this warp only
    }
}

// ---------------------------------------------------------------------------
extern "C" void kernel_launch(void* const* d_in, const int* in_sizes, int n_in,
                              void* d_out, int out_size)
{
    const float* pcd         = (const float*)d_in[0];
    const float* feats       = (const float*)d_in[1];
    const float* also_pts    = (const float*)d_in[2];
    const int*   also_labels = (const int*)d_in[3];
    const int*   row         = (const int*)d_in[4];
    const int*   col         = (const int*)d_in[5];
    const float* w_in        = (const float*)d_in[6];
    const float* b_in        = (const float*)d_in[7];
    const float* w1          = (const float*)d_in[8];
    const float* b1          = (const float*)d_in[9];
    const float* w2          = (const float*)d_in[10];
    const float* b2          = (const float*)d_in[11];
    const float* w_out       = (const float*)d_in[12];
    const float* b_out       = (const float*)d_in[13];

    int nPts = in_sizes[1] / 64;
    if (nPts > 100000) nPts = 100000;
    int nE = in_sizes[4];
    int nTiles = (nE + 127) / 128;
    int write_labels = ((long long)out_size >= 3LL * nE) ? 1 : 0;

    static int attr_done = 0;
    if (!attr_done) {
        cudaFuncSetAttribute(edge_mma_kernel,
                             cudaFuncAttributeMaxDynamicSharedMemorySize, SM_TOTAL);
        attr_done = 1;
    }

    int pgrid = (nPts + 127) / 128 + 16;   // last 16 blocks: weight split
    precompute_kernel<<<pgrid, 128>>>(feats, w_in, b_in, nPts, w1, w2);

    int grid = 148 * 3;
    if (grid > nTiles) grid = nTiles;
    edge_mma_kernel<<<grid, 128, SM_TOTAL>>>(pcd, also_pts, also_labels, row, col,
                                             w_in, b1, b2, w_out, b_out,
                                             (float*)d_out, nE, nTiles, write_labels);
}

// round 6
// speedup vs baseline: 4.6634x; 1.1933x over previous
#include <cuda_runtime.h>
#include <cuda_fp16.h>
#include <cstdint>

typedef unsigned long long ull;

// Precomputed g = feats @ w_in[0:64,:] + b_in  (N x 64)
__device__ float g_buf[100000 * 64];
// Packed fp16 weights: [w1, w2], each 64x64 fp16 = 2048 u32
__device__ uint32_t w_pack[2][2048];

// ---------------------------------------------------------------------------
// helpers
// ---------------------------------------------------------------------------
__device__ __forceinline__ ull pack2(float lo, float hi) {
    ull r; asm("mov.b64 %0, {%1, %2};" : "=l"(r) : "f"(lo), "f"(hi)); return r;
}
__device__ __forceinline__ ull bcast2(float v) { return pack2(v, v); }
__device__ __forceinline__ ull ffma2(ull a, ull b, ull c) {
    ull d; asm("fma.rn.f32x2 %0, %1, %2, %3;" : "=l"(d) : "l"(a), "l"(b), "l"(c)); return d;
}
__device__ __forceinline__ uint32_t smem_u32(const void* p) {
    uint32_t a;
    asm("{ .reg .u64 t; cvta.to.shared.u64 t, %1; cvt.u32.u64 %0, t; }" : "=r"(a) : "l"(p));
    return a;
}
__device__ __forceinline__ uint32_t pack_f16x2(float lo, float hi) {
    __half2 h = __floats2half2_rn(lo, hi);      // lo -> low half
    return *reinterpret_cast<uint32_t*>(&h);
}
__device__ __forceinline__ void ldsm_x4(uint32_t* r, uint32_t addr) {
    asm volatile("ldmatrix.sync.aligned.m8n8.x4.shared.b16 {%0,%1,%2,%3}, [%4];"
                 : "=r"(r[0]), "=r"(r[1]), "=r"(r[2]), "=r"(r[3]) : "r"(addr));
}
__device__ __forceinline__ void ldsm_x4_t(uint32_t* r, uint32_t addr) {
    asm volatile("ldmatrix.sync.aligned.m8n8.x4.trans.shared.b16 {%0,%1,%2,%3}, [%4];"
                 : "=r"(r[0]), "=r"(r[1]), "=r"(r[2]), "=r"(r[3]) : "r"(addr));
}
__device__ __forceinline__ void mma16816(float* c, const uint32_t* a, const uint32_t* b) {
    asm volatile(
        "mma.sync.aligned.m16n8k16.row.col.f32.f16.f16.f32 "
        "{%0,%1,%2,%3}, {%4,%5,%6,%7}, {%8,%9}, {%0,%1,%2,%3};"
        : "+f"(c[0]), "+f"(c[1]), "+f"(c[2]), "+f"(c[3])
        : "r"(a[0]), "r"(a[1]), "r"(a[2]), "r"(a[3]), "r"(b[0]), "r"(b[1]));
}

// ---------------------------------------------------------------------------
// Kernel 1: fused  (a) g[n,:] = feats[n,:] @ w_in[0:64,:] + b_in
//                  (b) last 16 blocks: fp16 conversion of w1, w2
// ---------------------------------------------------------------------------
__global__ void __launch_bounds__(128) precompute_kernel(
    const float* __restrict__ feats, const float* __restrict__ w_in,
    const float* __restrict__ b_in, int n_pts,
    const float* __restrict__ w1g, const float* __restrict__ w2g)
{
    if (blockIdx.x >= gridDim.x - 16) {
        int idx = (blockIdx.x - (gridDim.x - 16)) * 128 + threadIdx.x;  // 0..2047
        w_pack[0][idx] = pack_f16x2(w1g[2 * idx], w1g[2 * idx + 1]);
        w_pack[1][idx] = pack_f16x2(w2g[2 * idx], w2g[2 * idx + 1]);
        return;
    }

    __shared__ __align__(16) ull s_w[2048];
    for (int idx = threadIdx.x; idx < 2048; idx += 128)
        s_w[idx] = ((const ull*)w_in)[idx];
    __syncthreads();

    int n = blockIdx.x * 128 + threadIdx.x;
    if (n >= n_pts) return;

    float act[64];
    const float4* fp = (const float4*)(feats + (size_t)n * 64);
#pragma unroll
    for (int i = 0; i < 16; i++) {
        float4 v = fp[i];
        act[4 * i] = v.x; act[4 * i + 1] = v.y; act[4 * i + 2] = v.z; act[4 * i + 3] = v.w;
    }
    ull acc[32];
    const ull* bp = (const ull*)b_in;
#pragma unroll
    for (int j = 0; j < 32; j++) acc[j] = bp[j];
#pragma unroll
    for (int i = 0; i < 64; i++) {
        ull a2 = bcast2(act[i]);
#pragma unroll
        for (int j = 0; j < 32; j += 2) {
            ulonglong2 w = *reinterpret_cast<const ulonglong2*>(&s_w[i * 32 + j]);
            acc[j] = ffma2(a2, w.x, acc[j]);
            acc[j + 1] = ffma2(a2, w.y, acc[j + 1]);
        }
    }
    ull* gp = (ull*)(g_buf + (size_t)n * 64);
#pragma unroll
    for (int j = 0; j < 32; j++) gp[j] = acc[j];
}

// ---------------------------------------------------------------------------
// Kernel 2: persistent mma.sync edge MLP (plain fp16 weights).
// 128 edges/tile, 4 warps, 32 edges/warp.
// SMEM (bytes):
//   [0)      2 weight tiles [64][72 fp16] (144B stride): w1, w2
//   [18432)  A tile [128][72] fp16
//   [36864)  w3 (3x64 f32), [37632) w_out, [38144) b1, [38400) b2, [38656) b_out
// ---------------------------------------------------------------------------
#define SM_W     0
#define SM_A     18432
#define SM_W3    36864
#define SM_WOUT  37632
#define SM_B1    38144
#define SM_B2    38400
#define SM_BOUT  38656
#define SM_TOTAL 38912

__global__ void __launch_bounds__(128, 3) edge_mma_kernel(
    const float* __restrict__ pcd,
    const float* __restrict__ also_pts,
    const int* __restrict__ also_labels,
    const int* __restrict__ row,
    const int* __restrict__ col,
    const float* __restrict__ w_in,
    const float* __restrict__ b1g,
    const float* __restrict__ b2g,
    const float* __restrict__ w_outg, const float* __restrict__ b_outg,
    float* __restrict__ out,
    int nE, int nTiles, int write_labels)
{
    extern __shared__ __align__(16) char smem[];
    const int tid = threadIdx.x;
    const int lane = tid & 31;
    const int warp = tid >> 5;

    // ---- stage weights into SMEM (144B row stride, conflict-free ldsm) ----
#pragma unroll
    for (int m = 0; m < 2; m++) {
        for (int idx = tid; idx < 2048; idx += 128) {
            int rk = idx >> 5, cc = idx & 31;
            *(uint32_t*)(smem + SM_W + m * 9216 + rk * 144 + cc * 4) = w_pack[m][idx];
        }
    }
    float* s_w3 = (float*)(smem + SM_W3);
    float* s_wout = (float*)(smem + SM_WOUT);
    float* s_b1 = (float*)(smem + SM_B1);
    float* s_b2 = (float*)(smem + SM_B2);
    float* s_bout = (float*)(smem + SM_BOUT);
    for (int idx = tid; idx < 192; idx += 128) s_w3[idx] = w_in[64 * 64 + idx];
    if (tid < 128) s_wout[tid] = w_outg[tid];
    if (tid < 64) { s_b1[tid] = b1g[tid]; s_b2[tid] = b2g[tid]; }
    if (tid < 2) s_bout[tid] = b_outg[tid];
    __syncthreads();

    const uint32_t sbase = smem_u32(smem);
    const uint32_t sA = sbase + SM_A;

    const int a_row = (lane & 7) + ((lane >> 3) & 1) * 8;      // 0..15
    const int a_c8 = ((lane >> 4) & 1) * 8;                     // 0 / +8 cols
    const int b_row = (lane & 7) + ((lane >> 3) & 3) * 8;       // 0..31

    // preload first tile's indices
    int r = 0, c = 0;
    if (blockIdx.x < nTiles) {
        int e0 = blockIdx.x * 128 + tid;
        int ee = e0 < nE ? e0 : nE - 1;
        r = row[ee]; c = col[ee];
    }

    for (int tile = blockIdx.x; tile < nTiles; tile += gridDim.x) {
        const int e = tile * 128 + tid;
        const bool valid = e < nE;

        // ---- prefetch next tile's indices + g row (hides gather chain) ----
        int rn = r, cn = c;
        {
            int tn = tile + gridDim.x;
            if (tn < nTiles) {
                int en = tn * 128 + tid;
                int een = en < nE ? en : nE - 1;
                rn = row[een]; cn = col[een];
                const char* gp_n = (const char*)(g_buf + (size_t)cn * 64);
                asm volatile("prefetch.global.L1 [%0];" :: "l"(gp_n));
                asm volatile("prefetch.global.L1 [%0];" :: "l"(gp_n + 128));
                asm volatile("prefetch.global.L1 [%0];" :: "l"(also_pts + (size_t)rn * 3));
                asm volatile("prefetch.global.L1 [%0];" :: "l"(pcd + (size_t)cn * 3));
            }
        }

        const float p0 = also_pts[(size_t)r * 3 + 0] - pcd[(size_t)c * 3 + 0];
        const float p1 = also_pts[(size_t)r * 3 + 1] - pcd[(size_t)c * 3 + 1];
        const float p2 = also_pts[(size_t)r * 3 + 2] - pcd[(size_t)c * 3 + 2];

        // ---- stage A: a = relu(g[c] + pos @ w3) -> fp16 SMEM tile ----
        {
            const float4* gp = (const float4*)(g_buf + (size_t)c * 64);
            const uint32_t rbase = sA + tid * 144;
#pragma unroll
            for (int h = 0; h < 2; h++) {
                float a[32];
#pragma unroll
                for (int q = 0; q < 8; q++) {
                    float4 v = gp[8 * h + q];
                    a[4 * q] = v.x; a[4 * q + 1] = v.y; a[4 * q + 2] = v.z; a[4 * q + 3] = v.w;
                }
#pragma unroll
                for (int j = 0; j < 32; j++) {
                    int jj = 32 * h + j;
                    a[j] = fmaf(p0, s_w3[jj], fmaf(p1, s_w3[64 + jj], fmaf(p2, s_w3[128 + jj], a[j])));
                }
#pragma unroll
                for (int q = 0; q < 4; q++) {
                    uint32_t h4[4];
#pragma unroll
                    for (int p = 0; p < 4; p++)
                        h4[p] = pack_f16x2(fmaxf(a[8 * q + 2 * p], 0.0f),
                                           fmaxf(a[8 * q + 2 * p + 1], 0.0f));
                    asm volatile("st.shared.v4.b32 [%0], {%1,%2,%3,%4};" ::
                                 "r"(rbase + h * 64 + q * 16),
                                 "r"(h4[0]), "r"(h4[1]), "r"(h4[2]), "r"(h4[3]));
                }
            }
        }
        __syncwarp();

        // ---- load A fragments (layer 1) ----
        uint32_t A[2][4][4];
#pragma unroll
        for (int mt = 0; mt < 2; mt++) {
            const int rowm = warp * 32 + mt * 16 + a_row;
#pragma unroll
            for (int kt = 0; kt < 4; kt++)
                ldsm_x4(A[mt][kt], sA + (uint32_t)rowm * 144 + (kt * 16 + a_c8) * 2);
        }

        float C[2][8][4];

        // ===================== two hidden layers =====================
#pragma unroll
        for (int L = 0; L < 2; L++) {
#pragma unroll
            for (int mt = 0; mt < 2; mt++)
#pragma unroll
                for (int nt = 0; nt < 8; nt++)
#pragma unroll
                    for (int i = 0; i < 4; i++) C[mt][nt][i] = 0.0f;

            const uint32_t wbase = sbase + SM_W + L * 9216;
#pragma unroll
            for (int kg = 0; kg < 2; kg++) {
#pragma unroll
                for (int nt = 0; nt < 8; nt++) {
                    uint32_t B[4];
                    ldsm_x4_t(B, wbase + (uint32_t)(kg * 32 + b_row) * 144 + nt * 16);
#pragma unroll
                    for (int mt = 0; mt < 2; mt++) {
                        mma16816(C[mt][nt], A[mt][2 * kg], B);
                        mma16816(C[mt][nt], A[mt][2 * kg + 1], B + 2);
                    }
                }
            }

            if (L == 0) {
                // epilogue 1: x = relu(C + b1) -> new A fragments in registers
#pragma unroll
                for (int mt = 0; mt < 2; mt++) {
#pragma unroll
                    for (int kt = 0; kt < 4; kt++) {
#pragma unroll
                        for (int half = 0; half < 2; half++) {
                            const int nt = 2 * kt + half;
                            const int col0 = nt * 8 + (lane & 3) * 2;
                            float2 bb = *(const float2*)(s_b1 + col0);
                            A[mt][kt][2 * half + 0] =
                                pack_f16x2(fmaxf(C[mt][nt][0] + bb.x, 0.0f),
                                           fmaxf(C[mt][nt][1] + bb.y, 0.0f));
                            A[mt][kt][2 * half + 1] =
                                pack_f16x2(fmaxf(C[mt][nt][2] + bb.x, 0.0f),
                                           fmaxf(C[mt][nt][3] + bb.y, 0.0f));
                        }
                    }
                }
            }
        }

        // ---- final epilogue: logits = (C + b2) @ w_out + b_out; softmax ----
#pragma unroll
        for (int mt = 0; mt < 2; mt++) {
            float l0a = 0.0f, l1a = 0.0f, l0b = 0.0f, l1b = 0.0f;
#pragma unroll
            for (int nt = 0; nt < 8; nt++) {
                const int col0 = nt * 8 + (lane & 3) * 2;
                float2 bb = *(const float2*)(s_b2 + col0);
                float4 wo = *(const float4*)(s_wout + 2 * col0);
                float x0 = C[mt][nt][0] + bb.x;
                float x1 = C[mt][nt][1] + bb.y;
                float x2 = C[mt][nt][2] + bb.x;
                float x3 = C[mt][nt][3] + bb.y;
                l0a = fmaf(x0, wo.x, fmaf(x1, wo.z, l0a));
                l1a = fmaf(x0, wo.y, fmaf(x1, wo.w, l1a));
                l0b = fmaf(x2, wo.x, fmaf(x3, wo.z, l0b));
                l1b = fmaf(x2, wo.y, fmaf(x3, wo.w, l1b));
            }
#pragma unroll
            for (int off = 1; off <= 2; off <<= 1) {
                l0a += __shfl_xor_sync(0xFFFFFFFFu, l0a, off);
                l1a += __shfl_xor_sync(0xFFFFFFFFu, l1a, off);
                l0b += __shfl_xor_sync(0xFFFFFFFFu, l0b, off);
                l1b += __shfl_xor_sync(0xFFFFFFFFu, l1b, off);
            }
            if ((lane & 3) == 0) {
                const int e0 = tile * 128 + warp * 32 + mt * 16 + (lane >> 2);
                float la0 = l0a + s_bout[0], la1 = l1a + s_bout[1];
                float m0 = fmaxf(la0, la1);
                float ea = expf(la0 - m0), eb = expf(la1 - m0);
                float inv = 1.0f / (ea + eb);
                if (e0 < nE)
                    *(float2*)(out + 2 * (size_t)e0) = make_float2(ea * inv, eb * inv);

                const int e1 = e0 + 8;
                float lb0 = l0b + s_bout[0], lb1 = l1b + s_bout[1];
                float m1 = fmaxf(lb0, lb1);
                float ec = expf(lb0 - m1), ed = expf(lb1 - m1);
                float inv2 = 1.0f / (ec + ed);
                if (e1 < nE)
                    *(float2*)(out + 2 * (size_t)e1) = make_float2(ec * inv2, ed * inv2);
            }
        }

        if (write_labels && valid)
            out[2 * (size_t)nE + e] = (float)also_labels[r];

        r = rn; c = cn;
        __syncwarp();   // A-tile rows reused next iteration by this warp only
    }
}

// ---------------------------------------------------------------------------
extern "C" void kernel_launch(void* const* d_in, const int* in_sizes, int n_in,
                              void* d_out, int out_size)
{
    const float* pcd         = (const float*)d_in[0];
    const float* feats       = (const float*)d_in[1];
    const float* also_pts    = (const float*)d_in[2];
    const int*   also_labels = (const int*)d_in[3];
    const int*   row         = (const int*)d_in[4];
    const int*   col         = (const int*)d_in[5];
    const float* w_in        = (const float*)d_in[6];
    const float* b_in        = (const float*)d_in[7];
    const float* w1          = (const float*)d_in[8];
    const float* b1          = (const float*)d_in[9];
    const float* w2          = (const float*)d_in[10];
    const float* b2          = (const float*)d_in[11];
    const float* w_out       = (const float*)d_in[12];
    const float* b_out       = (const float*)d_in[13];

    int nPts = in_sizes[1] / 64;
    if (nPts > 100000) nPts = 100000;
    int nE = in_sizes[4];
    int nTiles = (nE + 127) / 128;
    int write_labels = ((long long)out_size >= 3LL * nE) ? 1 : 0;

    static int attr_done = 0;
    if (!attr_done) {
        cudaFuncSetAttribute(edge_mma_kernel,
                             cudaFuncAttributeMaxDynamicSharedMemorySize, SM_TOTAL);
        attr_done = 1;
    }

    int pgrid = (nPts + 127) / 128 + 16;   // last 16 blocks: weight convert
    precompute_kernel<<<pgrid, 128>>>(feats, w_in, b_in, nPts, w1, w2);

    int grid = 148 * 3;
    if (grid > nTiles) grid = nTiles;
    edge_mma_kernel<<<grid, 128, SM_TOTAL>>>(pcd, also_pts, also_labels, row, col,
                                             w_in, b1, b2, w_out, b_out,
                                             (float*)d_out, nE, nTiles, write_labels);
}

// round 7
// speedup vs baseline: 5.8244x; 1.2490x over previous
#include <cuda_runtime.h>
#include <cuda_fp16.h>
#include <cstdint>

typedef unsigned long long ull;

// Precomputed g = feats @ w_in[0:64,:] + b_in  (N x 64), stored fp16
__device__ __half g_buf[100000 * 64];
// Packed fp16 weights: [w1, w2], each 64x64 fp16 = 2048 u32
__device__ uint32_t w_pack[2][2048];

// ---------------------------------------------------------------------------
// helpers
// ---------------------------------------------------------------------------
__device__ __forceinline__ ull pack2(float lo, float hi) {
    ull r; asm("mov.b64 %0, {%1, %2};" : "=l"(r) : "f"(lo), "f"(hi)); return r;
}
__device__ __forceinline__ ull bcast2(float v) { return pack2(v, v); }
__device__ __forceinline__ ull ffma2(ull a, ull b, ull c) {
    ull d; asm("fma.rn.f32x2 %0, %1, %2, %3;" : "=l"(d) : "l"(a), "l"(b), "l"(c)); return d;
}
__device__ __forceinline__ void unpack2(ull v, float& lo, float& hi) {
    asm("mov.b64 {%0, %1}, %2;" : "=f"(lo), "=f"(hi) : "l"(v));
}
__device__ __forceinline__ uint32_t smem_u32(const void* p) {
    uint32_t a;
    asm("{ .reg .u64 t; cvta.to.shared.u64 t, %1; cvt.u32.u64 %0, t; }" : "=r"(a) : "l"(p));
    return a;
}
__device__ __forceinline__ uint32_t pack_f16x2(float lo, float hi) {
    __half2 h = __floats2half2_rn(lo, hi);      // lo -> low half
    return *reinterpret_cast<uint32_t*>(&h);
}
__device__ __forceinline__ void ldsm_x4(uint32_t* r, uint32_t addr) {
    asm volatile("ldmatrix.sync.aligned.m8n8.x4.shared.b16 {%0,%1,%2,%3}, [%4];"
                 : "=r"(r[0]), "=r"(r[1]), "=r"(r[2]), "=r"(r[3]) : "r"(addr));
}
__device__ __forceinline__ void ldsm_x4_t(uint32_t* r, uint32_t addr) {
    asm volatile("ldmatrix.sync.aligned.m8n8.x4.trans.shared.b16 {%0,%1,%2,%3}, [%4];"
                 : "=r"(r[0]), "=r"(r[1]), "=r"(r[2]), "=r"(r[3]) : "r"(addr));
}
__device__ __forceinline__ void mma16816(float* c, const uint32_t* a, const uint32_t* b) {
    asm volatile(
        "mma.sync.aligned.m16n8k16.row.col.f32.f16.f16.f32 "
        "{%0,%1,%2,%3}, {%4,%5,%6,%7}, {%8,%9}, {%0,%1,%2,%3};"
        : "+f"(c[0]), "+f"(c[1]), "+f"(c[2]), "+f"(c[3])
        : "r"(a[0]), "r"(a[1]), "r"(a[2]), "r"(a[3]), "r"(b[0]), "r"(b[1]));
}

// ---------------------------------------------------------------------------
// Kernel 1: fused  (a) g[n,:] = fp16(feats[n,:] @ w_in[0:64,:] + b_in)
//                  (b) last 16 blocks: fp16 conversion of w1, w2
// ---------------------------------------------------------------------------
__global__ void __launch_bounds__(128) precompute_kernel(
    const float* __restrict__ feats, const float* __restrict__ w_in,
    const float* __restrict__ b_in, int n_pts,
    const float* __restrict__ w1g, const float* __restrict__ w2g)
{
    if (blockIdx.x >= gridDim.x - 16) {
        int idx = (blockIdx.x - (gridDim.x - 16)) * 128 + threadIdx.x;  // 0..2047
        w_pack[0][idx] = pack_f16x2(w1g[2 * idx], w1g[2 * idx + 1]);
        w_pack[1][idx] = pack_f16x2(w2g[2 * idx], w2g[2 * idx + 1]);
        return;
    }

    __shared__ __align__(16) ull s_w[2048];
    for (int idx = threadIdx.x; idx < 2048; idx += 128)
        s_w[idx] = ((const ull*)w_in)[idx];
    __syncthreads();

    int n = blockIdx.x * 128 + threadIdx.x;
    if (n >= n_pts) return;

    float act[64];
    const float4* fp = (const float4*)(feats + (size_t)n * 64);
#pragma unroll
    for (int i = 0; i < 16; i++) {
        float4 v = fp[i];
        act[4 * i] = v.x; act[4 * i + 1] = v.y; act[4 * i + 2] = v.z; act[4 * i + 3] = v.w;
    }
    ull acc[32];
    const ull* bp = (const ull*)b_in;
#pragma unroll
    for (int j = 0; j < 32; j++) acc[j] = bp[j];
#pragma unroll
    for (int i = 0; i < 64; i++) {
        ull a2 = bcast2(act[i]);
#pragma unroll
        for (int j = 0; j < 32; j += 2) {
            ulonglong2 w = *reinterpret_cast<const ulonglong2*>(&s_w[i * 32 + j]);
            acc[j] = ffma2(a2, w.x, acc[j]);
            acc[j + 1] = ffma2(a2, w.y, acc[j + 1]);
        }
    }
    // convert to fp16 and store 128B row as 8 x uint4
    uint32_t h[32];
#pragma unroll
    for (int j = 0; j < 32; j++) {
        float f0, f1; unpack2(acc[j], f0, f1);
        h[j] = pack_f16x2(f0, f1);
    }
    uint4* gp = (uint4*)(g_buf + (size_t)n * 64);
#pragma unroll
    for (int q = 0; q < 8; q++)
        gp[q] = make_uint4(h[4 * q], h[4 * q + 1], h[4 * q + 2], h[4 * q + 3]);
}

// ---------------------------------------------------------------------------
// Kernel 2: persistent mma.sync edge MLP (plain fp16 weights, fp16 g gather).
// 128 edges/tile, 4 warps, 32 edges/warp.
// SMEM (bytes):
//   [0)      2 weight tiles [64][72 fp16] (144B stride): w1, w2
//   [18432)  A tile [128][72] fp16
//   [36864)  w3 (3x64 f32), [37632) w_out, [38144) b1, [38400) b2, [38656) b_out
// ---------------------------------------------------------------------------
#define SM_W     0
#define SM_A     18432
#define SM_W3    36864
#define SM_WOUT  37632
#define SM_B1    38144
#define SM_B2    38400
#define SM_BOUT  38656
#define SM_TOTAL 38912

__global__ void __launch_bounds__(128, 3) edge_mma_kernel(
    const float* __restrict__ pcd,
    const float* __restrict__ also_pts,
    const int* __restrict__ also_labels,
    const int* __restrict__ row,
    const int* __restrict__ col,
    const float* __restrict__ w_in,
    const float* __restrict__ b1g,
    const float* __restrict__ b2g,
    const float* __restrict__ w_outg, const float* __restrict__ b_outg,
    float* __restrict__ out,
    int nE, int nTiles, int write_labels)
{
    extern __shared__ __align__(16) char smem[];
    const int tid = threadIdx.x;
    const int lane = tid & 31;
    const int warp = tid >> 5;

    // ---- stage weights into SMEM (144B row stride, conflict-free ldsm) ----
#pragma unroll
    for (int m = 0; m < 2; m++) {
        for (int idx = tid; idx < 2048; idx += 128) {
            int rk = idx >> 5, cc = idx & 31;
            *(uint32_t*)(smem + SM_W + m * 9216 + rk * 144 + cc * 4) = w_pack[m][idx];
        }
    }
    float* s_w3 = (float*)(smem + SM_W3);
    float* s_wout = (float*)(smem + SM_WOUT);
    float* s_b1 = (float*)(smem + SM_B1);
    float* s_b2 = (float*)(smem + SM_B2);
    float* s_bout = (float*)(smem + SM_BOUT);
    for (int idx = tid; idx < 192; idx += 128) s_w3[idx] = w_in[64 * 64 + idx];
    if (tid < 128) s_wout[tid] = w_outg[tid];
    if (tid < 64) { s_b1[tid] = b1g[tid]; s_b2[tid] = b2g[tid]; }
    if (tid < 2) s_bout[tid] = b_outg[tid];
    __syncthreads();

    const uint32_t sbase = smem_u32(smem);
    const uint32_t sA = sbase + SM_A;

    const int a_row = (lane & 7) + ((lane >> 3) & 1) * 8;      // 0..15
    const int a_c8 = ((lane >> 4) & 1) * 8;                     // 0 / +8 cols
    const int b_row = (lane & 7) + ((lane >> 3) & 3) * 8;       // 0..31

    // preload first tile's indices
    int r = 0, c = 0;
    if (blockIdx.x < nTiles) {
        int e0 = blockIdx.x * 128 + tid;
        int ee = e0 < nE ? e0 : nE - 1;
        r = row[ee]; c = col[ee];
    }

    for (int tile = blockIdx.x; tile < nTiles; tile += gridDim.x) {
        const int e = tile * 128 + tid;
        const bool valid = e < nE;

        // ---- prefetch next tile's indices + g row (hides gather chain) ----
        int rn = r, cn = c;
        {
            int tn = tile + gridDim.x;
            if (tn < nTiles) {
                int en = tn * 128 + tid;
                int een = en < nE ? en : nE - 1;
                rn = row[een]; cn = col[een];
                const char* gp_n = (const char*)(g_buf + (size_t)cn * 64);
                asm volatile("prefetch.global.L1 [%0];" :: "l"(gp_n));
                asm volatile("prefetch.global.L1 [%0];" :: "l"(also_pts + (size_t)rn * 3));
                asm volatile("prefetch.global.L1 [%0];" :: "l"(pcd + (size_t)cn * 3));
            }
        }

        const float p0 = also_pts[(size_t)r * 3 + 0] - pcd[(size_t)c * 3 + 0];
        const float p1 = also_pts[(size_t)r * 3 + 1] - pcd[(size_t)c * 3 + 1];
        const float p2 = also_pts[(size_t)r * 3 + 2] - pcd[(size_t)c * 3 + 2];

        // ---- stage A: a = relu(g[c] + pos @ w3) -> fp16 SMEM tile ----
        {
            const uint4* gp = (const uint4*)(g_buf + (size_t)c * 64);  // 8 x 16B
            const uint32_t rbase = sA + tid * 144;
#pragma unroll
            for (int h = 0; h < 2; h++) {
                float a[32];
#pragma unroll
                for (int q = 0; q < 4; q++) {
                    uint4 v = gp[4 * h + q];
                    uint32_t w[4] = {v.x, v.y, v.z, v.w};
#pragma unroll
                    for (int p = 0; p < 4; p++) {
                        float2 f = __half22float2(*reinterpret_cast<__half2*>(&w[p]));
                        a[8 * q + 2 * p]     = f.x;
                        a[8 * q + 2 * p + 1] = f.y;
                    }
                }
#pragma unroll
                for (int j = 0; j < 32; j++) {
                    int jj = 32 * h + j;
                    a[j] = fmaf(p0, s_w3[jj], fmaf(p1, s_w3[64 + jj], fmaf(p2, s_w3[128 + jj], a[j])));
                }
#pragma unroll
                for (int q = 0; q < 4; q++) {
                    uint32_t h4[4];
#pragma unroll
                    for (int p = 0; p < 4; p++)
                        h4[p] = pack_f16x2(fmaxf(a[8 * q + 2 * p], 0.0f),
                                           fmaxf(a[8 * q + 2 * p + 1], 0.0f));
                    asm volatile("st.shared.v4.b32 [%0], {%1,%2,%3,%4};" ::
                                 "r"(rbase + h * 64 + q * 16),
                                 "r"(h4[0]), "r"(h4[1]), "r"(h4[2]), "r"(h4[3]));
                }
            }
        }
        __syncwarp();

        // ---- load A fragments (layer 1) ----
        uint32_t A[2][4][4];
#pragma unroll
        for (int mt = 0; mt < 2; mt++) {
            const int rowm = warp * 32 + mt * 16 + a_row;
#pragma unroll
            for (int kt = 0; kt < 4; kt++)
                ldsm_x4(A[mt][kt], sA + (uint32_t)rowm * 144 + (kt * 16 + a_c8) * 2);
        }

        float C[2][8][4];

        // ===================== two hidden layers =====================
#pragma unroll
        for (int L = 0; L < 2; L++) {
#pragma unroll
            for (int mt = 0; mt < 2; mt++)
#pragma unroll
                for (int nt = 0; nt < 8; nt++)
#pragma unroll
                    for (int i = 0; i < 4; i++) C[mt][nt][i] = 0.0f;

            const uint32_t wbase = sbase + SM_W + L * 9216;
#pragma unroll
            for (int kg = 0; kg < 2; kg++) {
#pragma unroll
                for (int nt = 0; nt < 8; nt++) {
                    uint32_t B[4];
                    ldsm_x4_t(B, wbase + (uint32_t)(kg * 32 + b_row) * 144 + nt * 16);
#pragma unroll
                    for (int mt = 0; mt < 2; mt++) {
                        mma16816(C[mt][nt], A[mt][2 * kg], B);
                        mma16816(C[mt][nt], A[mt][2 * kg + 1], B + 2);
                    }
                }
            }

            if (L == 0) {
                // epilogue 1: x = relu(C + b1) -> new A fragments in registers
#pragma unroll
                for (int mt = 0; mt < 2; mt++) {
#pragma unroll
                    for (int kt = 0; kt < 4; kt++) {
#pragma unroll
                        for (int half = 0; half < 2; half++) {
                            const int nt = 2 * kt + half;
                            const int col0 = nt * 8 + (lane & 3) * 2;
                            float2 bb = *(const float2*)(s_b1 + col0);
                            A[mt][kt][2 * half + 0] =
                                pack_f16x2(fmaxf(C[mt][nt][0] + bb.x, 0.0f),
                                           fmaxf(C[mt][nt][1] + bb.y, 0.0f));
                            A[mt][kt][2 * half + 1] =
                                pack_f16x2(fmaxf(C[mt][nt][2] + bb.x, 0.0f),
                                           fmaxf(C[mt][nt][3] + bb.y, 0.0f));
                        }
                    }
                }
            }
        }

        // ---- final epilogue: logits = (C + b2) @ w_out + b_out; softmax ----
#pragma unroll
        for (int mt = 0; mt < 2; mt++) {
            float l0a = 0.0f, l1a = 0.0f, l0b = 0.0f, l1b = 0.0f;
#pragma unroll
            for (int nt = 0; nt < 8; nt++) {
                const int col0 = nt * 8 + (lane & 3) * 2;
                float2 bb = *(const float2*)(s_b2 + col0);
                float4 wo = *(const float4*)(s_wout + 2 * col0);
                float x0 = C[mt][nt][0] + bb.x;
                float x1 = C[mt][nt][1] + bb.y;
                float x2 = C[mt][nt][2] + bb.x;
                float x3 = C[mt][nt][3] + bb.y;
                l0a = fmaf(x0, wo.x, fmaf(x1, wo.z, l0a));
                l1a = fmaf(x0, wo.y, fmaf(x1, wo.w, l1a));
                l0b = fmaf(x2, wo.x, fmaf(x3, wo.z, l0b));
                l1b = fmaf(x2, wo.y, fmaf(x3, wo.w, l1b));
            }
#pragma unroll
            for (int off = 1; off <= 2; off <<= 1) {
                l0a += __shfl_xor_sync(0xFFFFFFFFu, l0a, off);
                l1a += __shfl_xor_sync(0xFFFFFFFFu, l1a, off);
                l0b += __shfl_xor_sync(0xFFFFFFFFu, l0b, off);
                l1b += __shfl_xor_sync(0xFFFFFFFFu, l1b, off);
            }
            if ((lane & 3) == 0) {
                const int e0 = tile * 128 + warp * 32 + mt * 16 + (lane >> 2);
                float la0 = l0a + s_bout[0], la1 = l1a + s_bout[1];
                float m0 = fmaxf(la0, la1);
                float ea = expf(la0 - m0), eb = expf(la1 - m0);
                float inv = 1.0f / (ea + eb);
                if (e0 < nE)
                    *(float2*)(out + 2 * (size_t)e0) = make_float2(ea * inv, eb * inv);

                const int e1 = e0 + 8;
                float lb0 = l0b + s_bout[0], lb1 = l1b + s_bout[1];
                float m1 = fmaxf(lb0, lb1);
                float ec = expf(lb0 - m1), ed = expf(lb1 - m1);
                float inv2 = 1.0f / (ec + ed);
                if (e1 < nE)
                    *(float2*)(out + 2 * (size_t)e1) = make_float2(ec * inv2, ed * inv2);
            }
        }

        if (write_labels && valid)
            out[2 * (size_t)nE + e] = (float)also_labels[r];

        r = rn; c = cn;
        __syncwarp();   // A-tile rows reused next iteration by this warp only
    }
}

// ---------------------------------------------------------------------------
extern "C" void kernel_launch(void* const* d_in, const int* in_sizes, int n_in,
                              void* d_out, int out_size)
{
    const float* pcd         = (const float*)d_in[0];
    const float* feats       = (const float*)d_in[1];
    const float* also_pts    = (const float*)d_in[2];
    const int*   also_labels = (const int*)d_in[3];
    const int*   row         = (const int*)d_in[4];
    const int*   col         = (const int*)d_in[5];
    const float* w_in        = (const float*)d_in[6];
    const float* b_in        = (const float*)d_in[7];
    const float* w1          = (const float*)d_in[8];
    const float* b1          = (const float*)d_in[9];
    const float* w2          = (const float*)d_in[10];
    const float* b2          = (const float*)d_in[11];
    const float* w_out       = (const float*)d_in[12];
    const float* b_out       = (const float*)d_in[13];

    int nPts = in_sizes[1] / 64;
    if (nPts > 100000) nPts = 100000;
    int nE = in_sizes[4];
    int nTiles = (nE + 127) / 128;
    int write_labels = ((long long)out_size >= 3LL * nE) ? 1 : 0;

    static int attr_done = 0;
    if (!attr_done) {
        cudaFuncSetAttribute(edge_mma_kernel,
                             cudaFuncAttributeMaxDynamicSharedMemorySize, SM_TOTAL);
        attr_done = 1;
    }

    int pgrid = (nPts + 127) / 128 + 16;   // last 16 blocks: weight convert
    precompute_kernel<<<pgrid, 128>>>(feats, w_in, b_in, nPts, w1, w2);

    int grid = 148 * 3;
    if (grid > nTiles) grid = nTiles;
    edge_mma_kernel<<<grid, 128, SM_TOTAL>>>(pcd, also_pts, also_labels, row, col,
                                             w_in, b1, b2, w_out, b_out,
                                             (float*)d_out, nE, nTiles, write_labels);
}

// round 8
// speedup vs baseline: 6.4369x; 1.1052x over previous
#include <cuda_runtime.h>
#include <cuda_fp16.h>
#include <cstdint>

typedef unsigned long long ull;

// Precomputed g = feats @ w_in[0:64,:] + b_in  (N x 64), stored fp16
__device__ __half g_buf[100000 * 64];
// Packed fp16 weights: [w1, w2], each 64x64 fp16 = 2048 u32
__device__ uint32_t w_pack[2][2048];

// ---------------------------------------------------------------------------
// helpers
// ---------------------------------------------------------------------------
__device__ __forceinline__ ull pack2(float lo, float hi) {
    ull r; asm("mov.b64 %0, {%1, %2};" : "=l"(r) : "f"(lo), "f"(hi)); return r;
}
__device__ __forceinline__ ull bcast2(float v) { return pack2(v, v); }
__device__ __forceinline__ ull ffma2(ull a, ull b, ull c) {
    ull d; asm("fma.rn.f32x2 %0, %1, %2, %3;" : "=l"(d) : "l"(a), "l"(b), "l"(c)); return d;
}
__device__ __forceinline__ void unpack2(ull v, float& lo, float& hi) {
    asm("mov.b64 {%0, %1}, %2;" : "=f"(lo), "=f"(hi) : "l"(v));
}
__device__ __forceinline__ uint32_t smem_u32(const void* p) {
    uint32_t a;
    asm("{ .reg .u64 t; cvta.to.shared.u64 t, %1; cvt.u32.u64 %0, t; }" : "=r"(a) : "l"(p));
    return a;
}
__device__ __forceinline__ uint32_t pack_f16x2(float lo, float hi) {
    __half2 h = __floats2half2_rn(lo, hi);      // lo -> low half
    return *reinterpret_cast<uint32_t*>(&h);
}
__device__ __forceinline__ void ldsm_x4(uint32_t* r, uint32_t addr) {
    asm volatile("ldmatrix.sync.aligned.m8n8.x4.shared.b16 {%0,%1,%2,%3}, [%4];"
                 : "=r"(r[0]), "=r"(r[1]), "=r"(r[2]), "=r"(r[3]) : "r"(addr));
}
__device__ __forceinline__ void ldsm_x4_t(uint32_t* r, uint32_t addr) {
    asm volatile("ldmatrix.sync.aligned.m8n8.x4.trans.shared.b16 {%0,%1,%2,%3}, [%4];"
                 : "=r"(r[0]), "=r"(r[1]), "=r"(r[2]), "=r"(r[3]) : "r"(addr));
}
__device__ __forceinline__ void mma16816(float* c, const uint32_t* a, const uint32_t* b) {
    asm volatile(
        "mma.sync.aligned.m16n8k16.row.col.f32.f16.f16.f32 "
        "{%0,%1,%2,%3}, {%4,%5,%6,%7}, {%8,%9}, {%0,%1,%2,%3};"
        : "+f"(c[0]), "+f"(c[1]), "+f"(c[2]), "+f"(c[3])
        : "r"(a[0]), "r"(a[1]), "r"(a[2]), "r"(a[3]), "r"(b[0]), "r"(b[1]));
}

// ---------------------------------------------------------------------------
// Kernel 1: fused  (a) g[n,:] = fp16(feats[n,:] @ w_in[0:64,:] + b_in)
//                  (b) last 16 blocks: fp16 conversion of w1, w2
// ---------------------------------------------------------------------------
__global__ void __launch_bounds__(128) precompute_kernel(
    const float* __restrict__ feats, const float* __restrict__ w_in,
    const float* __restrict__ b_in, int n_pts,
    const float* __restrict__ w1g, const float* __restrict__ w2g)
{
    if (blockIdx.x >= gridDim.x - 16) {
        int idx = (blockIdx.x - (gridDim.x - 16)) * 128 + threadIdx.x;  // 0..2047
        w_pack[0][idx] = pack_f16x2(w1g[2 * idx], w1g[2 * idx + 1]);
        w_pack[1][idx] = pack_f16x2(w2g[2 * idx], w2g[2 * idx + 1]);
        return;
    }

    __shared__ __align__(16) ull s_w[2048];
    for (int idx = threadIdx.x; idx < 2048; idx += 128)
        s_w[idx] = ((const ull*)w_in)[idx];
    __syncthreads();

    int n = blockIdx.x * 128 + threadIdx.x;
    if (n >= n_pts) return;

    float act[64];
    const float4* fp = (const float4*)(feats + (size_t)n * 64);
#pragma unroll
    for (int i = 0; i < 16; i++) {
        float4 v = fp[i];
        act[4 * i] = v.x; act[4 * i + 1] = v.y; act[4 * i + 2] = v.z; act[4 * i + 3] = v.w;
    }
    ull acc[32];
    const ull* bp = (const ull*)b_in;
#pragma unroll
    for (int j = 0; j < 32; j++) acc[j] = bp[j];
#pragma unroll
    for (int i = 0; i < 64; i++) {
        ull a2 = bcast2(act[i]);
#pragma unroll
        for (int j = 0; j < 32; j += 2) {
            ulonglong2 w = *reinterpret_cast<const ulonglong2*>(&s_w[i * 32 + j]);
            acc[j] = ffma2(a2, w.x, acc[j]);
            acc[j + 1] = ffma2(a2, w.y, acc[j + 1]);
        }
    }
    uint32_t h[32];
#pragma unroll
    for (int j = 0; j < 32; j++) {
        float f0, f1; unpack2(acc[j], f0, f1);
        h[j] = pack_f16x2(f0, f1);
    }
    uint4* gp = (uint4*)(g_buf + (size_t)n * 64);
#pragma unroll
    for (int q = 0; q < 8; q++)
        gp[q] = make_uint4(h[4 * q], h[4 * q + 1], h[4 * q + 2], h[4 * q + 3]);
}

// ---------------------------------------------------------------------------
// Kernel 2: persistent mma.sync edge MLP.
// 128 edges/tile, 4 warps, 32 edges/warp. Cooperative g gather:
// 8 lanes fetch one edge's 128B row; pos@w3 fixup inline (w3 slice in regs).
// SMEM (bytes):
//   [0)      2 weight tiles [64][72 fp16] (144B stride): w1, w2
//   [18432)  A tile [128][72] fp16
//   [36864)  w3 (3x64 f32), [37632) w_out, [38144) b1, [38400) b2, [38656) b_out
// ---------------------------------------------------------------------------
#define SM_W     0
#define SM_A     18432
#define SM_W3    36864
#define SM_WOUT  37632
#define SM_B1    38144
#define SM_B2    38400
#define SM_BOUT  38656
#define SM_TOTAL 38912

__global__ void __launch_bounds__(128, 3) edge_mma_kernel(
    const float* __restrict__ pcd,
    const float* __restrict__ also_pts,
    const int* __restrict__ also_labels,
    const int* __restrict__ row,
    const int* __restrict__ col,
    const float* __restrict__ w_in,
    const float* __restrict__ b1g,
    const float* __restrict__ b2g,
    const float* __restrict__ w_outg, const float* __restrict__ b_outg,
    float* __restrict__ out,
    int nE, int nTiles, int write_labels)
{
    extern __shared__ __align__(16) char smem[];
    const int tid = threadIdx.x;
    const int lane = tid & 31;
    const int warp = tid >> 5;
    const uint32_t FULL = 0xFFFFFFFFu;

    // ---- stage weights into SMEM (144B row stride, conflict-free ldsm) ----
#pragma unroll
    for (int m = 0; m < 2; m++) {
        for (int idx = tid; idx < 2048; idx += 128) {
            int rk = idx >> 5, cc = idx & 31;
            *(uint32_t*)(smem + SM_W + m * 9216 + rk * 144 + cc * 4) = w_pack[m][idx];
        }
    }
    float* s_w3 = (float*)(smem + SM_W3);
    float* s_wout = (float*)(smem + SM_WOUT);
    float* s_b1 = (float*)(smem + SM_B1);
    float* s_b2 = (float*)(smem + SM_B2);
    float* s_bout = (float*)(smem + SM_BOUT);
    for (int idx = tid; idx < 192; idx += 128) s_w3[idx] = w_in[64 * 64 + idx];
    if (tid < 128) s_wout[tid] = w_outg[tid];
    if (tid < 64) { s_b1[tid] = b1g[tid]; s_b2[tid] = b2g[tid]; }
    if (tid < 2) s_bout[tid] = b_outg[tid];
    __syncthreads();

    const uint32_t sbase = smem_u32(smem);
    const uint32_t sA = sbase + SM_A;

    const int a_row = (lane & 7) + ((lane >> 3) & 1) * 8;      // 0..15
    const int a_c8 = ((lane >> 4) & 1) * 8;                     // 0 / +8 cols
    const int b_row = (lane & 7) + ((lane >> 3) & 3) * 8;       // 0..31

    // per-lane cooperative-gather mapping + w3 column slice (constant)
    const int esub = lane >> 3;          // which of 4 edges this lane serves
    const int part = lane & 7;           // which 16B chunk of the row
    float w3r[3][8];
#pragma unroll
    for (int rr = 0; rr < 3; rr++)
#pragma unroll
        for (int j = 0; j < 8; j++)
            w3r[rr][j] = s_w3[rr * 64 + part * 8 + j];

    // preload first tile's indices
    int r = 0, c = 0;
    if (blockIdx.x < nTiles) {
        int e0 = blockIdx.x * 128 + tid;
        int ee = e0 < nE ? e0 : nE - 1;
        r = row[ee]; c = col[ee];
    }

    for (int tile = blockIdx.x; tile < nTiles; tile += gridDim.x) {
        const int e = tile * 128 + tid;
        const bool valid = e < nE;

        // ---- prefetch next tile's indices + g row (hides gather chain) ----
        int rn = r, cn = c;
        {
            int tn = tile + gridDim.x;
            if (tn < nTiles) {
                int en = tn * 128 + tid;
                int een = en < nE ? en : nE - 1;
                rn = row[een]; cn = col[een];
                asm volatile("prefetch.global.L1 [%0];" :: "l"((const char*)(g_buf + (size_t)cn * 64)));
                asm volatile("prefetch.global.L1 [%0];" :: "l"(also_pts + (size_t)rn * 3));
                asm volatile("prefetch.global.L1 [%0];" :: "l"(pcd + (size_t)cn * 3));
            }
        }

        const float p0 = also_pts[(size_t)r * 3 + 0] - pcd[(size_t)c * 3 + 0];
        const float p1 = also_pts[(size_t)r * 3 + 1] - pcd[(size_t)c * 3 + 1];
        const float p2 = also_pts[(size_t)r * 3 + 2] - pcd[(size_t)c * 3 + 2];

        // ---- stage A (cooperative): 8 lanes per edge row.
        //      a = relu(g[c] + pos @ w3) -> fp16 SMEM tile ----
#pragma unroll
        for (int i = 0; i < 8; i++) {
            const int eg = 4 * i + esub;                       // edge-in-warp
            const int cg = __shfl_sync(FULL, c, eg);
            const float q0 = __shfl_sync(FULL, p0, eg);
            const float q1 = __shfl_sync(FULL, p1, eg);
            const float q2 = __shfl_sync(FULL, p2, eg);
            const uint4 v = *(const uint4*)(g_buf + (size_t)cg * 64 + part * 8);
            uint32_t w[4] = {v.x, v.y, v.z, v.w};
            uint32_t h4[4];
#pragma unroll
            for (int p = 0; p < 4; p++) {
                float2 f = __half22float2(*reinterpret_cast<__half2*>(&w[p]));
                float a0 = fmaf(q0, w3r[0][2 * p],
                           fmaf(q1, w3r[1][2 * p],
                           fmaf(q2, w3r[2][2 * p], f.x)));
                float a1 = fmaf(q0, w3r[0][2 * p + 1],
                           fmaf(q1, w3r[1][2 * p + 1],
                           fmaf(q2, w3r[2][2 * p + 1], f.y)));
                h4[p] = pack_f16x2(fmaxf(a0, 0.0f), fmaxf(a1, 0.0f));
            }
            asm volatile("st.shared.v4.b32 [%0], {%1,%2,%3,%4};" ::
                         "r"(sA + (uint32_t)(warp * 32 + eg) * 144 + part * 16),
                         "r"(h4[0]), "r"(h4[1]), "r"(h4[2]), "r"(h4[3]));
        }
        __syncwarp();

        // ---- load A fragments (layer 1) ----
        uint32_t A[2][4][4];
#pragma unroll
        for (int mt = 0; mt < 2; mt++) {
            const int rowm = warp * 32 + mt * 16 + a_row;
#pragma unroll
            for (int kt = 0; kt < 4; kt++)
                ldsm_x4(A[mt][kt], sA + (uint32_t)rowm * 144 + (kt * 16 + a_c8) * 2);
        }

        float C[2][8][4];

        // ===================== two hidden layers =====================
#pragma unroll
        for (int L = 0; L < 2; L++) {
#pragma unroll
            for (int mt = 0; mt < 2; mt++)
#pragma unroll
                for (int nt = 0; nt < 8; nt++)
#pragma unroll
                    for (int i = 0; i < 4; i++) C[mt][nt][i] = 0.0f;

            const uint32_t wbase = sbase + SM_W + L * 9216;
#pragma unroll
            for (int kg = 0; kg < 2; kg++) {
#pragma unroll
                for (int nt = 0; nt < 8; nt++) {
                    uint32_t B[4];
                    ldsm_x4_t(B, wbase + (uint32_t)(kg * 32 + b_row) * 144 + nt * 16);
#pragma unroll
                    for (int mt = 0; mt < 2; mt++) {
                        mma16816(C[mt][nt], A[mt][2 * kg], B);
                        mma16816(C[mt][nt], A[mt][2 * kg + 1], B + 2);
                    }
                }
            }

            if (L == 0) {
                // epilogue 1: x = relu(C + b1) -> new A fragments in registers
#pragma unroll
                for (int mt = 0; mt < 2; mt++) {
#pragma unroll
                    for (int kt = 0; kt < 4; kt++) {
#pragma unroll
                        for (int half = 0; half < 2; half++) {
                            const int nt = 2 * kt + half;
                            const int col0 = nt * 8 + (lane & 3) * 2;
                            float2 bb = *(const float2*)(s_b1 + col0);
                            A[mt][kt][2 * half + 0] =
                                pack_f16x2(fmaxf(C[mt][nt][0] + bb.x, 0.0f),
                                           fmaxf(C[mt][nt][1] + bb.y, 0.0f));
                            A[mt][kt][2 * half + 1] =
                                pack_f16x2(fmaxf(C[mt][nt][2] + bb.x, 0.0f),
                                           fmaxf(C[mt][nt][3] + bb.y, 0.0f));
                        }
                    }
                }
            }
        }

        // ---- final epilogue: logits = (C + b2) @ w_out + b_out; softmax ----
#pragma unroll
        for (int mt = 0; mt < 2; mt++) {
            float l0a = 0.0f, l1a = 0.0f, l0b = 0.0f, l1b = 0.0f;
#pragma unroll
            for (int nt = 0; nt < 8; nt++) {
                const int col0 = nt * 8 + (lane & 3) * 2;
                float2 bb = *(const float2*)(s_b2 + col0);
                float4 wo = *(const float4*)(s_wout + 2 * col0);
                float x0 = C[mt][nt][0] + bb.x;
                float x1 = C[mt][nt][1] + bb.y;
                float x2 = C[mt][nt][2] + bb.x;
                float x3 = C[mt][nt][3] + bb.y;
                l0a = fmaf(x0, wo.x, fmaf(x1, wo.z, l0a));
                l1a = fmaf(x0, wo.y, fmaf(x1, wo.w, l1a));
                l0b = fmaf(x2, wo.x, fmaf(x3, wo.z, l0b));
                l1b = fmaf(x2, wo.y, fmaf(x3, wo.w, l1b));
            }
#pragma unroll
            for (int off = 1; off <= 2; off <<= 1) {
                l0a += __shfl_xor_sync(FULL, l0a, off);
                l1a += __shfl_xor_sync(FULL, l1a, off);
                l0b += __shfl_xor_sync(FULL, l0b, off);
                l1b += __shfl_xor_sync(FULL, l1b, off);
            }
            if ((lane & 3) == 0) {
                const int e0 = tile * 128 + warp * 32 + mt * 16 + (lane >> 2);
                float la0 = l0a + s_bout[0], la1 = l1a + s_bout[1];
                float m0 = fmaxf(la0, la1);
                float ea = expf(la0 - m0), eb = expf(la1 - m0);
                float inv = 1.0f / (ea + eb);
                if (e0 < nE)
                    *(float2*)(out + 2 * (size_t)e0) = make_float2(ea * inv, eb * inv);

                const int e1 = e0 + 8;
                float lb0 = l0b + s_bout[0], lb1 = l1b + s_bout[1];
                float m1 = fmaxf(lb0, lb1);
                float ec = expf(lb0 - m1), ed = expf(lb1 - m1);
                float inv2 = 1.0f / (ec + ed);
                if (e1 < nE)
                    *(float2*)(out + 2 * (size_t)e1) = make_float2(ec * inv2, ed * inv2);
            }
        }

        if (write_labels && valid)
            out[2 * (size_t)nE + e] = (float)also_labels[r];

        r = rn; c = cn;
        __syncwarp();   // A-tile rows reused next iteration by this warp only
    }
}

// ---------------------------------------------------------------------------
extern "C" void kernel_launch(void* const* d_in, const int* in_sizes, int n_in,
                              void* d_out, int out_size)
{
    const float* pcd         = (const float*)d_in[0];
    const float* feats       = (const float*)d_in[1];
    const float* also_pts    = (const float*)d_in[2];
    const int*   also_labels = (const int*)d_in[3];
    const int*   row         = (const int*)d_in[4];
    const int*   col         = (const int*)d_in[5];
    const float* w_in        = (const float*)d_in[6];
    const float* b_in        = (const float*)d_in[7];
    const float* w1          = (const float*)d_in[8];
    const float* b1          = (const float*)d_in[9];
    const float* w2          = (const float*)d_in[10];
    const float* b2          = (const float*)d_in[11];
    const float* w_out       = (const float*)d_in[12];
    const float* b_out       = (const float*)d_in[13];

    int nPts = in_sizes[1] / 64;
    if (nPts > 100000) nPts = 100000;
    int nE = in_sizes[4];
    int nTiles = (nE + 127) / 128;
    int write_labels = ((long long)out_size >= 3LL * nE) ? 1 : 0;

    static int attr_done = 0;
    if (!attr_done) {
        cudaFuncSetAttribute(edge_mma_kernel,
                             cudaFuncAttributeMaxDynamicSharedMemorySize, SM_TOTAL);
        attr_done = 1;
    }

    int pgrid = (nPts + 127) / 128 + 16;   // last 16 blocks: weight convert
    precompute_kernel<<<pgrid, 128>>>(feats, w_in, b_in, nPts, w1, w2);

    int grid = 148 * 3;
    if (grid > nTiles) grid = nTiles;
    edge_mma_kernel<<<grid, 128, SM_TOTAL>>>(pcd, also_pts, also_labels, row, col,
                                             w_in, b1, b2, w_out, b_out,
                                             (float*)d_out, nE, nTiles, write_labels);
}